// round 2
// baseline (speedup 1.0000x reference)
#include <cuda_runtime.h>
#include <math.h>

// Problem constants (fixed by the reference)
#define HIDDEN 2048
#define NHEADS 16
#define HEADDIM 128
#define BATCH 2
#define SEQ 2048
#define MTOK (BATCH * SEQ)   // 4096

// ---------------------------------------------------------------------------
// Scratch buffers (allocation-free rule: __device__ globals)
// ---------------------------------------------------------------------------
__device__ float g_q[MTOK * HIDDEN];
__device__ float g_k[MTOK * HIDDEN];
__device__ float g_v[MTOK * HIDDEN];
__device__ float g_ao[MTOK * HIDDEN];

// ---------------------------------------------------------------------------
// GEMM: C[M,N] = A[M,K] @ W[K,N] + bias[N]
// 128x128x16 tiles, 256 threads, 8x8 microtile per thread.
// ---------------------------------------------------------------------------
#define BM 128
#define BN 128
#define BK 16
#define LDA (BM + 4)   // padded transposed A tile rows

__global__ __launch_bounds__(256)
void gemm_bias_kernel(const float* __restrict__ A,
                      const float* __restrict__ W,
                      const float* __restrict__ bias,
                      float* __restrict__ C,
                      int M, int N, int K)
{
    __shared__ float As[BK][LDA];   // transposed: As[k][m]
    __shared__ float Ws[BK][BN];    // natural:    Ws[k][n]

    const int tid = threadIdx.x;
    const int bm = blockIdx.y * BM;
    const int bn = blockIdx.x * BN;
    const int tr = tid >> 4;        // 0..15 -> rows tr*8
    const int tc = tid & 15;        // 0..15 -> cols tc*8

    float acc[8][8];
#pragma unroll
    for (int i = 0; i < 8; i++)
#pragma unroll
        for (int j = 0; j < 8; j++) acc[i][j] = 0.0f;

    for (int k0 = 0; k0 < K; k0 += BK) {
        // Load A tile (BM x BK) -> transposed into As[k][m]
#pragma unroll
        for (int r = 0; r < 2; r++) {
            int idx = tid + r * 256;          // 0..511
            int ar  = idx >> 2;               // 0..127
            int ac4 = idx & 3;                // 0..3
            float4 v = *(const float4*)(A + (size_t)(bm + ar) * K + k0 + ac4 * 4);
            As[ac4 * 4 + 0][ar] = v.x;
            As[ac4 * 4 + 1][ar] = v.y;
            As[ac4 * 4 + 2][ar] = v.z;
            As[ac4 * 4 + 3][ar] = v.w;
        }
        // Load W tile (BK x BN) natural
#pragma unroll
        for (int r = 0; r < 2; r++) {
            int idx = tid + r * 256;          // 0..511
            int wr  = idx >> 5;               // 0..15
            int wc4 = idx & 31;               // 0..31
            *(float4*)(&Ws[wr][wc4 * 4]) =
                *(const float4*)(W + (size_t)(k0 + wr) * N + bn + wc4 * 4);
        }
        __syncthreads();

#pragma unroll
        for (int k = 0; k < BK; k++) {
            float4 a0 = *(const float4*)(&As[k][tr * 8]);
            float4 a1 = *(const float4*)(&As[k][tr * 8 + 4]);
            float4 b0 = *(const float4*)(&Ws[k][tc * 8]);
            float4 b1 = *(const float4*)(&Ws[k][tc * 8 + 4]);
            float ra[8] = {a0.x, a0.y, a0.z, a0.w, a1.x, a1.y, a1.z, a1.w};
            float rb[8] = {b0.x, b0.y, b0.z, b0.w, b1.x, b1.y, b1.z, b1.w};
#pragma unroll
            for (int i = 0; i < 8; i++)
#pragma unroll
                for (int j = 0; j < 8; j++)
                    acc[i][j] = fmaf(ra[i], rb[j], acc[i][j]);
        }
        __syncthreads();
    }

    // Epilogue: bias + store
    float bb[8];
#pragma unroll
    for (int j = 0; j < 8; j++) bb[j] = bias[bn + tc * 8 + j];

#pragma unroll
    for (int i = 0; i < 8; i++) {
        size_t row = (size_t)(bm + tr * 8 + i);
        float4 o0, o1;
        o0.x = acc[i][0] + bb[0]; o0.y = acc[i][1] + bb[1];
        o0.z = acc[i][2] + bb[2]; o0.w = acc[i][3] + bb[3];
        o1.x = acc[i][4] + bb[4]; o1.y = acc[i][5] + bb[5];
        o1.z = acc[i][6] + bb[6]; o1.w = acc[i][7] + bb[7];
        *(float4*)(C + row * N + bn + tc * 8)     = o0;
        *(float4*)(C + row * N + bn + tc * 8 + 4) = o1;
    }
}

// ---------------------------------------------------------------------------
// Flash attention: per (b, h, q-tile of 64), stream KV in 64-row tiles.
// 256 threads. O accumulator in registers (each thread: 4 q-rows x 8 d-cols).
// Online softmax. fp32 throughout.
// ---------------------------------------------------------------------------
#define BQ 64
#define BKV 64
#define LDT 68   // padded row length for transposed Q/K tiles (mult of 4)

// smem layout (floats):
//  Qs : [128][LDT]   (Qs[d][q])         128*68
//  Ks : [128][LDT]   (Ks[d][kv])        128*68
//  Vs : [64][128]    (Vs[kv][d])        64*128
//  Pt : [64][64]     (Pt[kv][q])        64*64
//  mrow/lrow/srow : [64] each
#define SM_QS   0
#define SM_KS   (SM_QS + 128 * LDT)
#define SM_VS   (SM_KS + 128 * LDT)
#define SM_PT   (SM_VS + BKV * HEADDIM)
#define SM_M    (SM_PT + BKV * BQ)
#define SM_L    (SM_M + BQ)
#define SM_S    (SM_L + BQ)
#define SM_TOT  (SM_S + BQ)
#define ATTN_SMEM_BYTES (SM_TOT * sizeof(float))

__global__ __launch_bounds__(256)
void attn_kernel(const float* __restrict__ Q,
                 const float* __restrict__ K,
                 const float* __restrict__ V,
                 float* __restrict__ O)
{
    extern __shared__ float sm[];
    float* Qs   = sm + SM_QS;
    float* Ks   = sm + SM_KS;
    float* Vs   = sm + SM_VS;
    float* Pt   = sm + SM_PT;
    float* mrow = sm + SM_M;
    float* lrow = sm + SM_L;
    float* srow = sm + SM_S;

    const int tid = threadIdx.x;
    const int q0  = blockIdx.x * BQ;
    const int h   = blockIdx.y;
    const int b   = blockIdx.z;
    const size_t base = (size_t)b * SEQ * HIDDEN + (size_t)h * HEADDIM;

    const float scale = 0.08838834764831845f; // 1/sqrt(128)

    // Load Q tile (64 x 128), scaled, transposed into Qs[d][q]
#pragma unroll
    for (int r = 0; r < 8; r++) {
        int idx = tid + r * 256;      // 0..2047
        int q   = idx >> 5;           // 0..63
        int c4  = idx & 31;           // 0..31
        float4 v = *(const float4*)(Q + base + (size_t)(q0 + q) * HIDDEN + c4 * 4);
        Qs[(c4 * 4 + 0) * LDT + q] = v.x * scale;
        Qs[(c4 * 4 + 1) * LDT + q] = v.y * scale;
        Qs[(c4 * 4 + 2) * LDT + q] = v.z * scale;
        Qs[(c4 * 4 + 3) * LDT + q] = v.w * scale;
    }
    if (tid < BQ) { mrow[tid] = -INFINITY; lrow[tid] = 0.0f; }

    float o[4][8];
#pragma unroll
    for (int i = 0; i < 4; i++)
#pragma unroll
        for (int j = 0; j < 8; j++) o[i][j] = 0.0f;

    const int tq = tid >> 4;   // 0..15 -> q rows tq*4
    const int tk = tid & 15;   // 0..15 -> kv cols tk*4 (S phase), d cols tk*8 (O phase)

    __syncthreads();

    for (int kv0 = 0; kv0 < SEQ; kv0 += BKV) {
        // Load K (transposed) and V (natural)
#pragma unroll
        for (int r = 0; r < 8; r++) {
            int idx = tid + r * 256;
            int kr  = idx >> 5;
            int c4  = idx & 31;
            float4 kvv = *(const float4*)(K + base + (size_t)(kv0 + kr) * HIDDEN + c4 * 4);
            Ks[(c4 * 4 + 0) * LDT + kr] = kvv.x;
            Ks[(c4 * 4 + 1) * LDT + kr] = kvv.y;
            Ks[(c4 * 4 + 2) * LDT + kr] = kvv.z;
            Ks[(c4 * 4 + 3) * LDT + kr] = kvv.w;
            float4 vv = *(const float4*)(V + base + (size_t)(kv0 + kr) * HIDDEN + c4 * 4);
            *(float4*)(Vs + kr * HEADDIM + c4 * 4) = vv;
        }
        __syncthreads();

        // S = Q @ K^T  (64x64), each thread a 4x4 microtile
        float acc[4][4];
#pragma unroll
        for (int i = 0; i < 4; i++)
#pragma unroll
            for (int j = 0; j < 4; j++) acc[i][j] = 0.0f;

#pragma unroll 4
        for (int d = 0; d < HEADDIM; d++) {
            float4 qa = *(const float4*)(Qs + d * LDT + tq * 4);
            float4 kb = *(const float4*)(Ks + d * LDT + tk * 4);
            float ra[4] = {qa.x, qa.y, qa.z, qa.w};
            float rb[4] = {kb.x, kb.y, kb.z, kb.w};
#pragma unroll
            for (int i = 0; i < 4; i++)
#pragma unroll
                for (int j = 0; j < 4; j++)
                    acc[i][j] = fmaf(ra[i], rb[j], acc[i][j]);
        }
        // write S^T into Pt[kv][q]
#pragma unroll
        for (int j = 0; j < 4; j++)
#pragma unroll
            for (int i = 0; i < 4; i++)
                Pt[(tk * 4 + j) * BQ + (tq * 4 + i)] = acc[i][j];
        __syncthreads();

        // Online softmax per q-row (64 rows, one thread each)
        if (tid < BQ) {
            int r = tid;
            float m_old = mrow[r];
            float m_new = m_old;
#pragma unroll 4
            for (int j = 0; j < BKV; j++)
                m_new = fmaxf(m_new, Pt[j * BQ + r]);
            float sc = __expf(m_old - m_new);
            float lsum = 0.0f;
#pragma unroll 4
            for (int j = 0; j < BKV; j++) {
                float p = __expf(Pt[j * BQ + r] - m_new);
                Pt[j * BQ + r] = p;
                lsum += p;
            }
            mrow[r] = m_new;
            lrow[r] = lrow[r] * sc + lsum;
            srow[r] = sc;
        }
        __syncthreads();

        // Rescale O, then O += P @ V  (each thread: rows tq*4.., cols tk*8..)
        float rs[4];
#pragma unroll
        for (int i = 0; i < 4; i++) rs[i] = srow[tq * 4 + i];
#pragma unroll
        for (int i = 0; i < 4; i++)
#pragma unroll
            for (int j = 0; j < 8; j++) o[i][j] *= rs[i];

#pragma unroll 2
        for (int kv = 0; kv < BKV; kv++) {
            float4 p  = *(const float4*)(Pt + kv * BQ + tq * 4);
            float4 va = *(const float4*)(Vs + kv * HEADDIM + tk * 8);
            float4 vb = *(const float4*)(Vs + kv * HEADDIM + tk * 8 + 4);
            float rp[4] = {p.x, p.y, p.z, p.w};
            float rv[8] = {va.x, va.y, va.z, va.w, vb.x, vb.y, vb.z, vb.w};
#pragma unroll
            for (int i = 0; i < 4; i++)
#pragma unroll
                for (int j = 0; j < 8; j++)
                    o[i][j] = fmaf(rp[i], rv[j], o[i][j]);
        }
        __syncthreads();   // guard Ks/Vs/Pt before next tile overwrites
    }

    // Epilogue: normalize by l, store to [B,S,HIDDEN]
#pragma unroll
    for (int i = 0; i < 4; i++) {
        float inv = 1.0f / lrow[tq * 4 + i];
        size_t row = base + (size_t)(q0 + tq * 4 + i) * HIDDEN + tk * 8;
        float4 o0, o1;
        o0.x = o[i][0] * inv; o0.y = o[i][1] * inv;
        o0.z = o[i][2] * inv; o0.w = o[i][3] * inv;
        o1.x = o[i][4] * inv; o1.y = o[i][5] * inv;
        o1.z = o[i][6] * inv; o1.w = o[i][7] * inv;
        *(float4*)(O + row)     = o0;
        *(float4*)(O + row + 4) = o1;
    }
}

// ---------------------------------------------------------------------------
// Launch
// ---------------------------------------------------------------------------
extern "C" void kernel_launch(void* const* d_in, const int* in_sizes, int n_in,
                              void* d_out, int out_size)
{
    (void)in_sizes; (void)n_in; (void)out_size;

    const float* hs = (const float*)d_in[0];
    const float* wq = (const float*)d_in[1];
    const float* bq = (const float*)d_in[2];
    const float* wk = (const float*)d_in[3];
    const float* bk = (const float*)d_in[4];
    const float* wv = (const float*)d_in[5];
    const float* bv = (const float*)d_in[6];
    const float* wo = (const float*)d_in[7];
    const float* bo = (const float*)d_in[8];
    float* out = (float*)d_out;

    float *q, *k, *v, *ao;
    cudaGetSymbolAddress((void**)&q,  g_q);
    cudaGetSymbolAddress((void**)&k,  g_k);
    cudaGetSymbolAddress((void**)&v,  g_v);
    cudaGetSymbolAddress((void**)&ao, g_ao);

    cudaFuncSetAttribute(attn_kernel,
                         cudaFuncAttributeMaxDynamicSharedMemorySize,
                         (int)ATTN_SMEM_BYTES);

    dim3 gemm_grid(HIDDEN / BN, MTOK / BM);   // (16, 32)
    dim3 gemm_blk(256);

    // QKV projections
    gemm_bias_kernel<<<gemm_grid, gemm_blk>>>(hs, wq, bq, q, MTOK, HIDDEN, HIDDEN);
    gemm_bias_kernel<<<gemm_grid, gemm_blk>>>(hs, wk, bk, k, MTOK, HIDDEN, HIDDEN);
    gemm_bias_kernel<<<gemm_grid, gemm_blk>>>(hs, wv, bv, v, MTOK, HIDDEN, HIDDEN);

    // Attention
    dim3 attn_grid(SEQ / BQ, NHEADS, BATCH);  // (32, 16, 2)
    attn_kernel<<<attn_grid, 256, ATTN_SMEM_BYTES>>>(q, k, v, ao);

    // Output projection
    gemm_bias_kernel<<<gemm_grid, gemm_blk>>>(ao, wo, bo, out, MTOK, HIDDEN, HIDDEN);
}

// round 3
// speedup vs baseline: 1.4578x; 1.4578x over previous
#include <cuda_runtime.h>
#include <math.h>
#include <stdint.h>

// Problem constants (fixed by the reference)
#define HIDDEN 2048
#define NHEADS 16
#define HEADDIM 128
#define BATCH 2
#define SEQ 2048
#define MTOK (BATCH * SEQ)   // 4096

// ---------------------------------------------------------------------------
// Scratch buffers (allocation-free rule: __device__ globals)
// ---------------------------------------------------------------------------
__device__ float g_q[MTOK * HIDDEN];
__device__ float g_k[MTOK * HIDDEN];
__device__ float g_v[MTOK * HIDDEN];
__device__ float g_ao[MTOK * HIDDEN];

// ---------------------------------------------------------------------------
// TF32 tensor-core GEMM: C[M,N] = A[M,K] @ W[K,N] + bias[N]
// 128x128x32 block tile, 256 threads = 8 warps (2 x 4), warp tile 64x32,
// mma.sync.aligned.m16n8k8 tf32, explicit RNA rounding to tf32 in smem.
// ---------------------------------------------------------------------------
#define GBM 128
#define GBN 128
#define GBK 32

__device__ __forceinline__ uint32_t f2tf32(float f) {
    uint32_t r;
    asm("cvt.rna.tf32.f32 %0, %1;" : "=r"(r) : "f"(f));
    return r;
}

__device__ __forceinline__ void mma_tf32(float* c, const uint32_t* a, const uint32_t* b) {
    asm volatile(
        "mma.sync.aligned.m16n8k8.row.col.f32.tf32.tf32.f32 "
        "{%0,%1,%2,%3}, {%4,%5,%6,%7}, {%8,%9}, {%0,%1,%2,%3};\n"
        : "+f"(c[0]), "+f"(c[1]), "+f"(c[2]), "+f"(c[3])
        : "r"(a[0]), "r"(a[1]), "r"(a[2]), "r"(a[3]), "r"(b[0]), "r"(b[1]));
}

__global__ __launch_bounds__(256)
void gemm_tf32_kernel(const float* __restrict__ A,
                      const float* __restrict__ W,
                      const float* __restrict__ bias,
                      float* __restrict__ C,
                      int M, int N, int K)
{
    __shared__ uint32_t As[GBM][GBK + 4];   // [m][k], pad 4 -> frag loads conflict-free
    __shared__ uint32_t Bs[GBK][GBN + 8];   // [k][n], pad 8 -> frag loads conflict-free

    const int tid  = threadIdx.x;
    const int lane = tid & 31;
    const int warp = tid >> 5;
    const int wm   = warp >> 2;      // 0..1 -> rows wm*64
    const int wn   = warp & 3;       // 0..3 -> cols wn*32
    const int g    = lane >> 2;      // 0..7
    const int tig  = lane & 3;       // 0..3

    const int bm = blockIdx.y * GBM;
    const int bn = blockIdx.x * GBN;

    // global load indices (A: 128x32 tile; B: 32x128 tile; 4 float4 each)
    const int a_r0 = tid >> 3;        // 0..31  (+32*i)
    const int a_c  = (tid & 7) * 4;   // 0,4,..28
    const int b_r0 = tid >> 5;        // 0..7   (+8*i)
    const int b_c  = (tid & 31) * 4;  // 0,4,..124

    float acc[4][4][4];
#pragma unroll
    for (int mi = 0; mi < 4; mi++)
#pragma unroll
        for (int ni = 0; ni < 4; ni++)
#pragma unroll
            for (int r = 0; r < 4; r++) acc[mi][ni][r] = 0.0f;

    const int nk = K / GBK;   // 64

    // ---- initial tile -> smem ----
#pragma unroll
    for (int i = 0; i < 4; i++) {
        int ar = a_r0 + 32 * i;
        float4 v = *(const float4*)(A + (size_t)(bm + ar) * K + a_c);
        uint4 t = { f2tf32(v.x), f2tf32(v.y), f2tf32(v.z), f2tf32(v.w) };
        *(uint4*)&As[ar][a_c] = t;

        int br = b_r0 + 8 * i;
        float4 w = *(const float4*)(W + (size_t)br * N + bn + b_c);
        uint4 u = { f2tf32(w.x), f2tf32(w.y), f2tf32(w.z), f2tf32(w.w) };
        *(uint4*)&Bs[br][b_c] = u;
    }
    __syncthreads();

    for (int kt = 0; kt < nk; kt++) {
        // ---- prefetch next tile into registers ----
        float4 pa[4], pb[4];
        if (kt + 1 < nk) {
            int k0 = (kt + 1) * GBK;
#pragma unroll
            for (int i = 0; i < 4; i++) {
                int ar = a_r0 + 32 * i;
                pa[i] = *(const float4*)(A + (size_t)(bm + ar) * K + k0 + a_c);
                int br = b_r0 + 8 * i;
                pb[i] = *(const float4*)(W + (size_t)(k0 + br) * N + bn + b_c);
            }
        }

        // ---- compute on current smem tile ----
#pragma unroll
        for (int ks = 0; ks < 4; ks++) {
            const int kk = ks * 8;
            uint32_t af[4][4], bf[4][2];
#pragma unroll
            for (int mi = 0; mi < 4; mi++) {
                int m = wm * 64 + mi * 16;
                af[mi][0] = As[m + g][kk + tig];
                af[mi][1] = As[m + g + 8][kk + tig];
                af[mi][2] = As[m + g][kk + tig + 4];
                af[mi][3] = As[m + g + 8][kk + tig + 4];
            }
#pragma unroll
            for (int ni = 0; ni < 4; ni++) {
                int n = wn * 32 + ni * 8;
                bf[ni][0] = Bs[kk + tig][n + g];
                bf[ni][1] = Bs[kk + tig + 4][n + g];
            }
#pragma unroll
            for (int mi = 0; mi < 4; mi++)
#pragma unroll
                for (int ni = 0; ni < 4; ni++)
                    mma_tf32(acc[mi][ni], af[mi], bf[ni]);
        }
        __syncthreads();

        // ---- store prefetched tile ----
        if (kt + 1 < nk) {
#pragma unroll
            for (int i = 0; i < 4; i++) {
                int ar = a_r0 + 32 * i;
                uint4 t = { f2tf32(pa[i].x), f2tf32(pa[i].y), f2tf32(pa[i].z), f2tf32(pa[i].w) };
                *(uint4*)&As[ar][a_c] = t;
                int br = b_r0 + 8 * i;
                uint4 u = { f2tf32(pb[i].x), f2tf32(pb[i].y), f2tf32(pb[i].z), f2tf32(pb[i].w) };
                *(uint4*)&Bs[br][b_c] = u;
            }
            __syncthreads();
        }
    }

    // ---- epilogue: bias + store (rows g, g+8; cols 2*tig, 2*tig+1) ----
#pragma unroll
    for (int ni = 0; ni < 4; ni++) {
        int col = bn + wn * 32 + ni * 8 + tig * 2;
        float b0 = bias[col], b1 = bias[col + 1];
#pragma unroll
        for (int mi = 0; mi < 4; mi++) {
            int row = bm + wm * 64 + mi * 16 + g;
            float2 r0 = { acc[mi][ni][0] + b0, acc[mi][ni][1] + b1 };
            float2 r1 = { acc[mi][ni][2] + b0, acc[mi][ni][3] + b1 };
            *(float2*)(C + (size_t)row * N + col)       = r0;
            *(float2*)(C + (size_t)(row + 8) * N + col) = r1;
        }
    }
}

// ---------------------------------------------------------------------------
// Flash attention (unchanged this round): per (b, h, q-tile of 64),
// stream KV in 64-row tiles, 256 threads, online softmax, fp32.
// ---------------------------------------------------------------------------
#define BQ 64
#define BKV 64
#define LDT 68

#define SM_QS   0
#define SM_KS   (SM_QS + 128 * LDT)
#define SM_VS   (SM_KS + 128 * LDT)
#define SM_PT   (SM_VS + BKV * HEADDIM)
#define SM_M    (SM_PT + BKV * BQ)
#define SM_L    (SM_M + BQ)
#define SM_S    (SM_L + BQ)
#define SM_TOT  (SM_S + BQ)
#define ATTN_SMEM_BYTES (SM_TOT * sizeof(float))

__global__ __launch_bounds__(256)
void attn_kernel(const float* __restrict__ Q,
                 const float* __restrict__ K,
                 const float* __restrict__ V,
                 float* __restrict__ O)
{
    extern __shared__ float sm[];
    float* Qs   = sm + SM_QS;
    float* Ks   = sm + SM_KS;
    float* Vs   = sm + SM_VS;
    float* Pt   = sm + SM_PT;
    float* mrow = sm + SM_M;
    float* lrow = sm + SM_L;
    float* srow = sm + SM_S;

    const int tid = threadIdx.x;
    const int q0  = blockIdx.x * BQ;
    const int h   = blockIdx.y;
    const int b   = blockIdx.z;
    const size_t base = (size_t)b * SEQ * HIDDEN + (size_t)h * HEADDIM;

    const float scale = 0.08838834764831845f; // 1/sqrt(128)

#pragma unroll
    for (int r = 0; r < 8; r++) {
        int idx = tid + r * 256;
        int q   = idx >> 5;
        int c4  = idx & 31;
        float4 v = *(const float4*)(Q + base + (size_t)(q0 + q) * HIDDEN + c4 * 4);
        Qs[(c4 * 4 + 0) * LDT + q] = v.x * scale;
        Qs[(c4 * 4 + 1) * LDT + q] = v.y * scale;
        Qs[(c4 * 4 + 2) * LDT + q] = v.z * scale;
        Qs[(c4 * 4 + 3) * LDT + q] = v.w * scale;
    }
    if (tid < BQ) { mrow[tid] = -INFINITY; lrow[tid] = 0.0f; }

    float o[4][8];
#pragma unroll
    for (int i = 0; i < 4; i++)
#pragma unroll
        for (int j = 0; j < 8; j++) o[i][j] = 0.0f;

    const int tq = tid >> 4;
    const int tk = tid & 15;

    __syncthreads();

    for (int kv0 = 0; kv0 < SEQ; kv0 += BKV) {
#pragma unroll
        for (int r = 0; r < 8; r++) {
            int idx = tid + r * 256;
            int kr  = idx >> 5;
            int c4  = idx & 31;
            float4 kvv = *(const float4*)(K + base + (size_t)(kv0 + kr) * HIDDEN + c4 * 4);
            Ks[(c4 * 4 + 0) * LDT + kr] = kvv.x;
            Ks[(c4 * 4 + 1) * LDT + kr] = kvv.y;
            Ks[(c4 * 4 + 2) * LDT + kr] = kvv.z;
            Ks[(c4 * 4 + 3) * LDT + kr] = kvv.w;
            float4 vv = *(const float4*)(V + base + (size_t)(kv0 + kr) * HIDDEN + c4 * 4);
            *(float4*)(Vs + kr * HEADDIM + c4 * 4) = vv;
        }
        __syncthreads();

        float acc[4][4];
#pragma unroll
        for (int i = 0; i < 4; i++)
#pragma unroll
            for (int j = 0; j < 4; j++) acc[i][j] = 0.0f;

#pragma unroll 4
        for (int d = 0; d < HEADDIM; d++) {
            float4 qa = *(const float4*)(Qs + d * LDT + tq * 4);
            float4 kb = *(const float4*)(Ks + d * LDT + tk * 4);
            float ra[4] = {qa.x, qa.y, qa.z, qa.w};
            float rb[4] = {kb.x, kb.y, kb.z, kb.w};
#pragma unroll
            for (int i = 0; i < 4; i++)
#pragma unroll
                for (int j = 0; j < 4; j++)
                    acc[i][j] = fmaf(ra[i], rb[j], acc[i][j]);
        }
#pragma unroll
        for (int j = 0; j < 4; j++)
#pragma unroll
            for (int i = 0; i < 4; i++)
                Pt[(tk * 4 + j) * BQ + (tq * 4 + i)] = acc[i][j];
        __syncthreads();

        if (tid < BQ) {
            int r = tid;
            float m_old = mrow[r];
            float m_new = m_old;
#pragma unroll 4
            for (int j = 0; j < BKV; j++)
                m_new = fmaxf(m_new, Pt[j * BQ + r]);
            float sc = __expf(m_old - m_new);
            float lsum = 0.0f;
#pragma unroll 4
            for (int j = 0; j < BKV; j++) {
                float p = __expf(Pt[j * BQ + r] - m_new);
                Pt[j * BQ + r] = p;
                lsum += p;
            }
            mrow[r] = m_new;
            lrow[r] = lrow[r] * sc + lsum;
            srow[r] = sc;
        }
        __syncthreads();

        float rs[4];
#pragma unroll
        for (int i = 0; i < 4; i++) rs[i] = srow[tq * 4 + i];
#pragma unroll
        for (int i = 0; i < 4; i++)
#pragma unroll
            for (int j = 0; j < 8; j++) o[i][j] *= rs[i];

#pragma unroll 2
        for (int kv = 0; kv < BKV; kv++) {
            float4 p  = *(const float4*)(Pt + kv * BQ + tq * 4);
            float4 va = *(const float4*)(Vs + kv * HEADDIM + tk * 8);
            float4 vb = *(const float4*)(Vs + kv * HEADDIM + tk * 8 + 4);
            float rp[4] = {p.x, p.y, p.z, p.w};
            float rv[8] = {va.x, va.y, va.z, va.w, vb.x, vb.y, vb.z, vb.w};
#pragma unroll
            for (int i = 0; i < 4; i++)
#pragma unroll
                for (int j = 0; j < 8; j++)
                    o[i][j] = fmaf(rp[i], rv[j], o[i][j]);
        }
        __syncthreads();
    }

#pragma unroll
    for (int i = 0; i < 4; i++) {
        float inv = 1.0f / lrow[tq * 4 + i];
        size_t row = base + (size_t)(q0 + tq * 4 + i) * HIDDEN + tk * 8;
        float4 o0, o1;
        o0.x = o[i][0] * inv; o0.y = o[i][1] * inv;
        o0.z = o[i][2] * inv; o0.w = o[i][3] * inv;
        o1.x = o[i][4] * inv; o1.y = o[i][5] * inv;
        o1.z = o[i][6] * inv; o1.w = o[i][7] * inv;
        *(float4*)(O + row)     = o0;
        *(float4*)(O + row + 4) = o1;
    }
}

// ---------------------------------------------------------------------------
// Launch
// ---------------------------------------------------------------------------
extern "C" void kernel_launch(void* const* d_in, const int* in_sizes, int n_in,
                              void* d_out, int out_size)
{
    (void)in_sizes; (void)n_in; (void)out_size;

    const float* hs = (const float*)d_in[0];
    const float* wq = (const float*)d_in[1];
    const float* bq = (const float*)d_in[2];
    const float* wk = (const float*)d_in[3];
    const float* bk = (const float*)d_in[4];
    const float* wv = (const float*)d_in[5];
    const float* bv = (const float*)d_in[6];
    const float* wo = (const float*)d_in[7];
    const float* bo = (const float*)d_in[8];
    float* out = (float*)d_out;

    float *q, *k, *v, *ao;
    cudaGetSymbolAddress((void**)&q,  g_q);
    cudaGetSymbolAddress((void**)&k,  g_k);
    cudaGetSymbolAddress((void**)&v,  g_v);
    cudaGetSymbolAddress((void**)&ao, g_ao);

    cudaFuncSetAttribute(attn_kernel,
                         cudaFuncAttributeMaxDynamicSharedMemorySize,
                         (int)ATTN_SMEM_BYTES);

    dim3 gemm_grid(HIDDEN / GBN, MTOK / GBM);   // (16, 32)
    dim3 gemm_blk(256);

    // QKV projections (tf32 tensor cores)
    gemm_tf32_kernel<<<gemm_grid, gemm_blk>>>(hs, wq, bq, q, MTOK, HIDDEN, HIDDEN);
    gemm_tf32_kernel<<<gemm_grid, gemm_blk>>>(hs, wk, bk, k, MTOK, HIDDEN, HIDDEN);
    gemm_tf32_kernel<<<gemm_grid, gemm_blk>>>(hs, wv, bv, v, MTOK, HIDDEN, HIDDEN);

    // Attention (fp32 SIMT, unchanged)
    dim3 attn_grid(SEQ / BQ, NHEADS, BATCH);  // (32, 16, 2)
    attn_kernel<<<attn_grid, 256, ATTN_SMEM_BYTES>>>(q, k, v, ao);

    // Output projection (tf32 tensor cores)
    gemm_tf32_kernel<<<gemm_grid, gemm_blk>>>(ao, wo, bo, out, MTOK, HIDDEN, HIDDEN);
}

// round 5
// speedup vs baseline: 3.2371x; 2.2206x over previous
#include <cuda_runtime.h>
#include <math.h>
#include <stdint.h>

// Problem constants (fixed by the reference)
#define HIDDEN 2048
#define NHEADS 16
#define HEADDIM 128
#define BATCH 2
#define SEQ 2048
#define MTOK (BATCH * SEQ)   // 4096

// ---------------------------------------------------------------------------
// Scratch buffers (allocation-free rule: __device__ globals)
// ---------------------------------------------------------------------------
__device__ float g_q[MTOK * HIDDEN];
__device__ float g_k[MTOK * HIDDEN];
__device__ float g_v[MTOK * HIDDEN];
__device__ float g_ao[MTOK * HIDDEN];

__device__ __forceinline__ uint32_t f2tf32(float f) {
    uint32_t r;
    asm("cvt.rna.tf32.f32 %0, %1;" : "=r"(r) : "f"(f));
    return r;
}

__device__ __forceinline__ void mma_tf32(float* c, const uint32_t* a, const uint32_t* b) {
    asm volatile(
        "mma.sync.aligned.m16n8k8.row.col.f32.tf32.tf32.f32 "
        "{%0,%1,%2,%3}, {%4,%5,%6,%7}, {%8,%9}, {%0,%1,%2,%3};\n"
        : "+f"(c[0]), "+f"(c[1]), "+f"(c[2]), "+f"(c[3])
        : "r"(a[0]), "r"(a[1]), "r"(a[2]), "r"(a[3]), "r"(b[0]), "r"(b[1]));
}

// ---------------------------------------------------------------------------
// TF32 tensor-core GEMM: C[M,N] = A[M,K] @ W[K,N] + bias[N]  (unchanged)
// ---------------------------------------------------------------------------
#define GBM 128
#define GBN 128
#define GBK 32

__global__ __launch_bounds__(256)
void gemm_tf32_kernel(const float* __restrict__ A,
                      const float* __restrict__ W,
                      const float* __restrict__ bias,
                      float* __restrict__ C,
                      int M, int N, int K)
{
    __shared__ uint32_t As[GBM][GBK + 4];
    __shared__ uint32_t Bs[GBK][GBN + 8];

    const int tid  = threadIdx.x;
    const int lane = tid & 31;
    const int warp = tid >> 5;
    const int wm   = warp >> 2;
    const int wn   = warp & 3;
    const int g    = lane >> 2;
    const int tig  = lane & 3;

    const int bm = blockIdx.y * GBM;
    const int bn = blockIdx.x * GBN;

    const int a_r0 = tid >> 3;
    const int a_c  = (tid & 7) * 4;
    const int b_r0 = tid >> 5;
    const int b_c  = (tid & 31) * 4;

    float acc[4][4][4];
#pragma unroll
    for (int mi = 0; mi < 4; mi++)
#pragma unroll
        for (int ni = 0; ni < 4; ni++)
#pragma unroll
            for (int r = 0; r < 4; r++) acc[mi][ni][r] = 0.0f;

    const int nk = K / GBK;

#pragma unroll
    for (int i = 0; i < 4; i++) {
        int ar = a_r0 + 32 * i;
        float4 v = *(const float4*)(A + (size_t)(bm + ar) * K + a_c);
        uint4 t = { f2tf32(v.x), f2tf32(v.y), f2tf32(v.z), f2tf32(v.w) };
        *(uint4*)&As[ar][a_c] = t;

        int br = b_r0 + 8 * i;
        float4 w = *(const float4*)(W + (size_t)br * N + bn + b_c);
        uint4 u = { f2tf32(w.x), f2tf32(w.y), f2tf32(w.z), f2tf32(w.w) };
        *(uint4*)&Bs[br][b_c] = u;
    }
    __syncthreads();

    for (int kt = 0; kt < nk; kt++) {
        float4 pa[4], pb[4];
        if (kt + 1 < nk) {
            int k0 = (kt + 1) * GBK;
#pragma unroll
            for (int i = 0; i < 4; i++) {
                int ar = a_r0 + 32 * i;
                pa[i] = *(const float4*)(A + (size_t)(bm + ar) * K + k0 + a_c);
                int br = b_r0 + 8 * i;
                pb[i] = *(const float4*)(W + (size_t)(k0 + br) * N + bn + b_c);
            }
        }

#pragma unroll
        for (int ks = 0; ks < 4; ks++) {
            const int kk = ks * 8;
            uint32_t af[4][4], bf[4][2];
#pragma unroll
            for (int mi = 0; mi < 4; mi++) {
                int m = wm * 64 + mi * 16;
                af[mi][0] = As[m + g][kk + tig];
                af[mi][1] = As[m + g + 8][kk + tig];
                af[mi][2] = As[m + g][kk + tig + 4];
                af[mi][3] = As[m + g + 8][kk + tig + 4];
            }
#pragma unroll
            for (int ni = 0; ni < 4; ni++) {
                int n = wn * 32 + ni * 8;
                bf[ni][0] = Bs[kk + tig][n + g];
                bf[ni][1] = Bs[kk + tig + 4][n + g];
            }
#pragma unroll
            for (int mi = 0; mi < 4; mi++)
#pragma unroll
                for (int ni = 0; ni < 4; ni++)
                    mma_tf32(acc[mi][ni], af[mi], bf[ni]);
        }
        __syncthreads();

        if (kt + 1 < nk) {
#pragma unroll
            for (int i = 0; i < 4; i++) {
                int ar = a_r0 + 32 * i;
                uint4 t = { f2tf32(pa[i].x), f2tf32(pa[i].y), f2tf32(pa[i].z), f2tf32(pa[i].w) };
                *(uint4*)&As[ar][a_c] = t;
                int br = b_r0 + 8 * i;
                uint4 u = { f2tf32(pb[i].x), f2tf32(pb[i].y), f2tf32(pb[i].z), f2tf32(pb[i].w) };
                *(uint4*)&Bs[br][b_c] = u;
            }
            __syncthreads();
        }
    }

#pragma unroll
    for (int ni = 0; ni < 4; ni++) {
        int col = bn + wn * 32 + ni * 8 + tig * 2;
        float b0 = bias[col], b1 = bias[col + 1];
#pragma unroll
        for (int mi = 0; mi < 4; mi++) {
            int row = bm + wm * 64 + mi * 16 + g;
            float2 r0 = { acc[mi][ni][0] + b0, acc[mi][ni][1] + b1 };
            float2 r1 = { acc[mi][ni][2] + b0, acc[mi][ni][3] + b1 };
            *(float2*)(C + (size_t)row * N + col)       = r0;
            *(float2*)(C + (size_t)(row + 8) * N + col) = r1;
        }
    }
}

// ---------------------------------------------------------------------------
// Tensor-core flash attention.
// Block: 256 threads (8 warps), BQ=128 q rows, BKV=64 kv per tile.
// S-phase: warp grid 4x2, warp tile 32x32.  PV: warp grid 4x2, warp tile 32x64.
// ---------------------------------------------------------------------------
#define ABQ 128
#define ABKV 64
#define LDQS 132   // Qs [128 q][d] stride  -> a-frag reads conflict-free
#define LDVS 136   // Vs [64 kv][d] stride  -> b-frag reads conflict-free
#define LDPS 66    // Ps [128 q][kv] stride -> EVEN so float2 stores stay 8B-aligned

// Ks swizzled [d][kv]: conflict-free transposed scalar stores AND b-frag reads
__device__ __forceinline__ int ks_idx(int d, int kv) {
    int x = ((d & 3) << 3) ^ ((d >> 2) & 31);
    return d * 64 + (kv ^ x);
}

#define AS_QS 0
#define AS_KS (AS_QS + ABQ * LDQS)            // 128*132 = 16896
#define AS_VS (AS_KS + HEADDIM * 64)          // + 8192
#define AS_PS (AS_VS + ABKV * LDVS)           // + 8704
#define AS_M  (AS_PS + ABQ * LDPS)            // + 8448
#define AS_L  (AS_M + ABQ)
#define AS_S  (AS_L + ABQ)
#define AS_TOT (AS_S + ABQ)
#define ATTN_SMEM_BYTES (AS_TOT * sizeof(float))   // ~170 KB

__global__ __launch_bounds__(256)
void attn_tc_kernel(const float* __restrict__ Q,
                    const float* __restrict__ K,
                    const float* __restrict__ V,
                    float* __restrict__ O)
{
    extern __shared__ float sm[];
    uint32_t* Qs = (uint32_t*)(sm + AS_QS);
    uint32_t* Ks = (uint32_t*)(sm + AS_KS);
    uint32_t* Vs = (uint32_t*)(sm + AS_VS);
    float*    Ps = sm + AS_PS;
    uint32_t* Pu = (uint32_t*)Ps;
    float* mrow = sm + AS_M;
    float* lrow = sm + AS_L;
    float* srow = sm + AS_S;

    const int tid  = threadIdx.x;
    const int lane = tid & 31;
    const int warp = tid >> 5;
    const int g    = lane >> 2;
    const int tig  = lane & 3;
    const int wm   = warp >> 1;    // 0..3 -> q rows wm*32
    const int wn   = warp & 1;     // 0..1 -> 32-col (S) / 64-col (PV) slab

    const int q0 = blockIdx.x * ABQ;
    const int h  = blockIdx.y;
    const int b  = blockIdx.z;
    const size_t base = (size_t)b * SEQ * HIDDEN + (size_t)h * HEADDIM;

    const float scale = 0.08838834764831845f;  // 1/sqrt(128)

    // ---- Load Q tile (128 x 128), scaled, tf32, natural layout ----
#pragma unroll
    for (int r = 0; r < 16; r++) {
        int q  = (tid >> 5) + 8 * r;
        int dg = lane * 4;
        float4 v = *(const float4*)(Q + base + (size_t)(q0 + q) * HIDDEN + dg);
        uint4 t = { f2tf32(v.x * scale), f2tf32(v.y * scale),
                    f2tf32(v.z * scale), f2tf32(v.w * scale) };
        *(uint4*)&Qs[q * LDQS + dg] = t;
    }
    if (tid < ABQ) { mrow[tid] = -INFINITY; lrow[tid] = 0.0f; }

    float o[2][8][4];
#pragma unroll
    for (int mi = 0; mi < 2; mi++)
#pragma unroll
        for (int nj = 0; nj < 8; nj++)
#pragma unroll
            for (int r = 0; r < 4; r++) o[mi][nj][r] = 0.0f;

    for (int kv0 = 0; kv0 < SEQ; kv0 += ABKV) {
        // ---- Load K (transposed+swizzled) and V (natural), tf32 ----
#pragma unroll
        for (int r = 0; r < 8; r++) {
            int kv = (tid >> 5) + 8 * r;
            int dg = lane * 4;
            float4 kq = *(const float4*)(K + base + (size_t)(kv0 + kv) * HIDDEN + dg);
            Ks[ks_idx(dg + 0, kv)] = f2tf32(kq.x);
            Ks[ks_idx(dg + 1, kv)] = f2tf32(kq.y);
            Ks[ks_idx(dg + 2, kv)] = f2tf32(kq.z);
            Ks[ks_idx(dg + 3, kv)] = f2tf32(kq.w);
            float4 vv = *(const float4*)(V + base + (size_t)(kv0 + kv) * HIDDEN + dg);
            uint4 u = { f2tf32(vv.x), f2tf32(vv.y), f2tf32(vv.z), f2tf32(vv.w) };
            *(uint4*)&Vs[kv * LDVS + dg] = u;
        }
        __syncthreads();

        // ---- S = Q @ K^T : warp tile 32x32 at (wm*32, wn*32) ----
        float sacc[2][4][4];
#pragma unroll
        for (int mi = 0; mi < 2; mi++)
#pragma unroll
            for (int ni = 0; ni < 4; ni++)
#pragma unroll
                for (int r = 0; r < 4; r++) sacc[mi][ni][r] = 0.0f;

#pragma unroll
        for (int ks = 0; ks < 16; ks++) {
            const int kk = ks * 8;
            uint32_t af[2][4], bf[4][2];
#pragma unroll
            for (int mi = 0; mi < 2; mi++) {
                int m = wm * 32 + mi * 16;
                af[mi][0] = Qs[(m + g) * LDQS + kk + tig];
                af[mi][1] = Qs[(m + g + 8) * LDQS + kk + tig];
                af[mi][2] = Qs[(m + g) * LDQS + kk + tig + 4];
                af[mi][3] = Qs[(m + g + 8) * LDQS + kk + tig + 4];
            }
#pragma unroll
            for (int ni = 0; ni < 4; ni++) {
                int n = wn * 32 + ni * 8;
                bf[ni][0] = Ks[ks_idx(kk + tig, n + g)];
                bf[ni][1] = Ks[ks_idx(kk + tig + 4, n + g)];
            }
#pragma unroll
            for (int mi = 0; mi < 2; mi++)
#pragma unroll
                for (int ni = 0; ni < 4; ni++)
                    mma_tf32(sacc[mi][ni], af[mi], bf[ni]);
        }
        // store scores
#pragma unroll
        for (int mi = 0; mi < 2; mi++) {
            int row = wm * 32 + mi * 16 + g;
#pragma unroll
            for (int ni = 0; ni < 4; ni++) {
                int col = wn * 32 + ni * 8 + tig * 2;
                float2 s0 = { sacc[mi][ni][0], sacc[mi][ni][1] };
                float2 s1 = { sacc[mi][ni][2], sacc[mi][ni][3] };
                *(float2*)&Ps[row * LDPS + col]       = s0;
                *(float2*)&Ps[(row + 8) * LDPS + col] = s1;
            }
        }
        __syncthreads();

        // ---- Online softmax: 2 threads per q-row ----
        {
            int r  = tid >> 1;
            int c0 = (tid & 1) * 32;
            float mloc = -INFINITY;
#pragma unroll 8
            for (int c = 0; c < 32; c++)
                mloc = fmaxf(mloc, Ps[r * LDPS + c0 + c]);
            mloc = fmaxf(mloc, __shfl_xor_sync(0xFFFFFFFF, mloc, 1));
            float m_old = mrow[r];
            float m_new = fmaxf(m_old, mloc);
            float sc = __expf(m_old - m_new);
            float ls = 0.0f;
#pragma unroll 8
            for (int c = 0; c < 32; c++) {
                float p = __expf(Ps[r * LDPS + c0 + c] - m_new);
                uint32_t pb = f2tf32(p);
                Pu[r * LDPS + c0 + c] = pb;
                ls += __uint_as_float(pb);
            }
            ls += __shfl_xor_sync(0xFFFFFFFF, ls, 1);
            if ((tid & 1) == 0) {
                mrow[r] = m_new;
                lrow[r] = lrow[r] * sc + ls;
                srow[r] = sc;
            }
        }
        __syncthreads();

        // ---- O rescale + O += P @ V : warp tile 32x64 at (wm*32, wn*64) ----
#pragma unroll
        for (int mi = 0; mi < 2; mi++) {
            int r0 = wm * 32 + mi * 16 + g;
            float s0 = srow[r0], s1 = srow[r0 + 8];
#pragma unroll
            for (int nj = 0; nj < 8; nj++) {
                o[mi][nj][0] *= s0; o[mi][nj][1] *= s0;
                o[mi][nj][2] *= s1; o[mi][nj][3] *= s1;
            }
        }
#pragma unroll
        for (int ks = 0; ks < 8; ks++) {
            const int kk = ks * 8;
            uint32_t af[2][4], bf[8][2];
#pragma unroll
            for (int mi = 0; mi < 2; mi++) {
                int m = wm * 32 + mi * 16;
                af[mi][0] = Pu[(m + g) * LDPS + kk + tig];
                af[mi][1] = Pu[(m + g + 8) * LDPS + kk + tig];
                af[mi][2] = Pu[(m + g) * LDPS + kk + tig + 4];
                af[mi][3] = Pu[(m + g + 8) * LDPS + kk + tig + 4];
            }
#pragma unroll
            for (int nj = 0; nj < 8; nj++) {
                int n = wn * 64 + nj * 8;
                bf[nj][0] = Vs[(kk + tig) * LDVS + n + g];
                bf[nj][1] = Vs[(kk + tig + 4) * LDVS + n + g];
            }
#pragma unroll
            for (int mi = 0; mi < 2; mi++)
#pragma unroll
                for (int nj = 0; nj < 8; nj++)
                    mma_tf32(o[mi][nj], af[mi], bf[nj]);
        }
        __syncthreads();
    }

    // ---- Epilogue: normalize by l, store ----
#pragma unroll
    for (int mi = 0; mi < 2; mi++) {
        int r0 = wm * 32 + mi * 16 + g;
        float inv0 = 1.0f / lrow[r0];
        float inv1 = 1.0f / lrow[r0 + 8];
#pragma unroll
        for (int nj = 0; nj < 8; nj++) {
            int col = wn * 64 + nj * 8 + tig * 2;
            float2 a = { o[mi][nj][0] * inv0, o[mi][nj][1] * inv0 };
            float2 c = { o[mi][nj][2] * inv1, o[mi][nj][3] * inv1 };
            *(float2*)(O + base + (size_t)(q0 + r0) * HIDDEN + col)     = a;
            *(float2*)(O + base + (size_t)(q0 + r0 + 8) * HIDDEN + col) = c;
        }
    }
}

// ---------------------------------------------------------------------------
// Launch
// ---------------------------------------------------------------------------
extern "C" void kernel_launch(void* const* d_in, const int* in_sizes, int n_in,
                              void* d_out, int out_size)
{
    (void)in_sizes; (void)n_in; (void)out_size;

    const float* hs = (const float*)d_in[0];
    const float* wq = (const float*)d_in[1];
    const float* bq = (const float*)d_in[2];
    const float* wk = (const float*)d_in[3];
    const float* bk = (const float*)d_in[4];
    const float* wv = (const float*)d_in[5];
    const float* bv = (const float*)d_in[6];
    const float* wo = (const float*)d_in[7];
    const float* bo = (const float*)d_in[8];
    float* out = (float*)d_out;

    float *q, *k, *v, *ao;
    cudaGetSymbolAddress((void**)&q,  g_q);
    cudaGetSymbolAddress((void**)&k,  g_k);
    cudaGetSymbolAddress((void**)&v,  g_v);
    cudaGetSymbolAddress((void**)&ao, g_ao);

    cudaFuncSetAttribute(attn_tc_kernel,
                         cudaFuncAttributeMaxDynamicSharedMemorySize,
                         (int)ATTN_SMEM_BYTES);

    dim3 gemm_grid(HIDDEN / GBN, MTOK / GBM);   // (16, 32)
    dim3 gemm_blk(256);

    gemm_tf32_kernel<<<gemm_grid, gemm_blk>>>(hs, wq, bq, q, MTOK, HIDDEN, HIDDEN);
    gemm_tf32_kernel<<<gemm_grid, gemm_blk>>>(hs, wk, bk, k, MTOK, HIDDEN, HIDDEN);
    gemm_tf32_kernel<<<gemm_grid, gemm_blk>>>(hs, wv, bv, v, MTOK, HIDDEN, HIDDEN);

    dim3 attn_grid(SEQ / ABQ, NHEADS, BATCH);   // (16, 16, 2)
    attn_tc_kernel<<<attn_grid, 256, ATTN_SMEM_BYTES>>>(q, k, v, ao);

    gemm_tf32_kernel<<<gemm_grid, gemm_blk>>>(ao, wo, bo, out, MTOK, HIDDEN, HIDDEN);
}

// round 6
// speedup vs baseline: 3.3549x; 1.0364x over previous
#include <cuda_runtime.h>
#include <math.h>
#include <stdint.h>

// Problem constants (fixed by the reference)
#define HIDDEN 2048
#define NHEADS 16
#define HEADDIM 128
#define BATCH 2
#define SEQ 2048
#define MTOK (BATCH * SEQ)   // 4096

// ---------------------------------------------------------------------------
// Scratch buffers (allocation-free rule: __device__ globals)
// ---------------------------------------------------------------------------
__device__ float g_q[MTOK * HIDDEN];
__device__ float g_k[MTOK * HIDDEN];
__device__ float g_v[MTOK * HIDDEN];
__device__ float g_ao[MTOK * HIDDEN];

__device__ __forceinline__ uint32_t f2tf32(float f) {
    uint32_t r;
    asm("cvt.rna.tf32.f32 %0, %1;" : "=r"(r) : "f"(f));
    return r;
}

__device__ __forceinline__ void mma_tf32(float* c, const uint32_t* a, const uint32_t* b) {
    asm volatile(
        "mma.sync.aligned.m16n8k8.row.col.f32.tf32.tf32.f32 "
        "{%0,%1,%2,%3}, {%4,%5,%6,%7}, {%8,%9}, {%0,%1,%2,%3};\n"
        : "+f"(c[0]), "+f"(c[1]), "+f"(c[2]), "+f"(c[3])
        : "r"(a[0]), "r"(a[1]), "r"(a[2]), "r"(a[3]), "r"(b[0]), "r"(b[1]));
}

// ---------------------------------------------------------------------------
// TF32 tensor-core GEMM: C[M,N] = A[M,K] @ W[K,N] + bias[N]
// 128x128x32 tile, 256 threads, now pinned to 2 CTAs/SM (regs <= 128).
// ---------------------------------------------------------------------------
#define GBM 128
#define GBN 128
#define GBK 32

__global__ __launch_bounds__(256, 2)
void gemm_tf32_kernel(const float* __restrict__ A,
                      const float* __restrict__ W,
                      const float* __restrict__ bias,
                      float* __restrict__ C,
                      int M, int N, int K)
{
    __shared__ uint32_t As[GBM][GBK + 4];
    __shared__ uint32_t Bs[GBK][GBN + 8];

    const int tid  = threadIdx.x;
    const int lane = tid & 31;
    const int warp = tid >> 5;
    const int wm   = warp >> 2;
    const int wn   = warp & 3;
    const int g    = lane >> 2;
    const int tig  = lane & 3;

    const int bm = blockIdx.y * GBM;
    const int bn = blockIdx.x * GBN;

    const int a_r0 = tid >> 3;
    const int a_c  = (tid & 7) * 4;
    const int b_r0 = tid >> 5;
    const int b_c  = (tid & 31) * 4;

    float acc[4][4][4];
#pragma unroll
    for (int mi = 0; mi < 4; mi++)
#pragma unroll
        for (int ni = 0; ni < 4; ni++)
#pragma unroll
            for (int r = 0; r < 4; r++) acc[mi][ni][r] = 0.0f;

    const int nk = K / GBK;

#pragma unroll
    for (int i = 0; i < 4; i++) {
        int ar = a_r0 + 32 * i;
        float4 v = *(const float4*)(A + (size_t)(bm + ar) * K + a_c);
        uint4 t = { f2tf32(v.x), f2tf32(v.y), f2tf32(v.z), f2tf32(v.w) };
        *(uint4*)&As[ar][a_c] = t;

        int br = b_r0 + 8 * i;
        float4 w = *(const float4*)(W + (size_t)br * N + bn + b_c);
        uint4 u = { f2tf32(w.x), f2tf32(w.y), f2tf32(w.z), f2tf32(w.w) };
        *(uint4*)&Bs[br][b_c] = u;
    }
    __syncthreads();

    for (int kt = 0; kt < nk; kt++) {
        float4 pa[4], pb[4];
        if (kt + 1 < nk) {
            int k0 = (kt + 1) * GBK;
#pragma unroll
            for (int i = 0; i < 4; i++) {
                int ar = a_r0 + 32 * i;
                pa[i] = *(const float4*)(A + (size_t)(bm + ar) * K + k0 + a_c);
                int br = b_r0 + 8 * i;
                pb[i] = *(const float4*)(W + (size_t)(k0 + br) * N + bn + b_c);
            }
        }

#pragma unroll
        for (int ks = 0; ks < 4; ks++) {
            const int kk = ks * 8;
            uint32_t af[4][4], bf[4][2];
#pragma unroll
            for (int mi = 0; mi < 4; mi++) {
                int m = wm * 64 + mi * 16;
                af[mi][0] = As[m + g][kk + tig];
                af[mi][1] = As[m + g + 8][kk + tig];
                af[mi][2] = As[m + g][kk + tig + 4];
                af[mi][3] = As[m + g + 8][kk + tig + 4];
            }
#pragma unroll
            for (int ni = 0; ni < 4; ni++) {
                int n = wn * 32 + ni * 8;
                bf[ni][0] = Bs[kk + tig][n + g];
                bf[ni][1] = Bs[kk + tig + 4][n + g];
            }
#pragma unroll
            for (int mi = 0; mi < 4; mi++)
#pragma unroll
                for (int ni = 0; ni < 4; ni++)
                    mma_tf32(acc[mi][ni], af[mi], bf[ni]);
        }
        __syncthreads();

        if (kt + 1 < nk) {
#pragma unroll
            for (int i = 0; i < 4; i++) {
                int ar = a_r0 + 32 * i;
                uint4 t = { f2tf32(pa[i].x), f2tf32(pa[i].y), f2tf32(pa[i].z), f2tf32(pa[i].w) };
                *(uint4*)&As[ar][a_c] = t;
                int br = b_r0 + 8 * i;
                uint4 u = { f2tf32(pb[i].x), f2tf32(pb[i].y), f2tf32(pb[i].z), f2tf32(pb[i].w) };
                *(uint4*)&Bs[br][b_c] = u;
            }
            __syncthreads();
        }
    }

#pragma unroll
    for (int ni = 0; ni < 4; ni++) {
        int col = bn + wn * 32 + ni * 8 + tig * 2;
        float b0 = bias[col], b1 = bias[col + 1];
#pragma unroll
        for (int mi = 0; mi < 4; mi++) {
            int row = bm + wm * 64 + mi * 16 + g;
            float2 r0 = { acc[mi][ni][0] + b0, acc[mi][ni][1] + b1 };
            float2 r1 = { acc[mi][ni][2] + b0, acc[mi][ni][3] + b1 };
            *(float2*)(C + (size_t)row * N + col)       = r0;
            *(float2*)(C + (size_t)(row + 8) * N + col) = r1;
        }
    }
}

// ---------------------------------------------------------------------------
// Tensor-core flash attention, 512 threads (16 warps), BQ=128, BKV=64.
// S-phase: warp grid 4x4, warp tile 32x16.  PV: warp grid 4x4, warp tile 32x32.
// ---------------------------------------------------------------------------
#define ABQ 128
#define ABKV 64
#define LDQS 132   // Qs [128 q][d] stride  -> a-frag reads conflict-free
#define LDVS 136   // Vs [64 kv][d] stride  -> b-frag reads conflict-free
#define LDPS 66    // Ps [128 q][kv] stride -> even (8B-aligned float2 stores)

// Ks swizzled [d][kv]: conflict-free transposed scalar stores AND b-frag reads
__device__ __forceinline__ int ks_idx(int d, int kv) {
    int x = ((d & 3) << 3) ^ ((d >> 2) & 31);
    return d * 64 + (kv ^ x);
}

#define AS_QS 0
#define AS_KS (AS_QS + ABQ * LDQS)
#define AS_VS (AS_KS + HEADDIM * 64)
#define AS_PS (AS_VS + ABKV * LDVS)
#define AS_M  (AS_PS + ABQ * LDPS)
#define AS_L  (AS_M + ABQ)
#define AS_S  (AS_L + ABQ)
#define AS_TOT (AS_S + ABQ)
#define ATTN_SMEM_BYTES (AS_TOT * sizeof(float))   // ~170 KB

__global__ __launch_bounds__(512)
void attn_tc_kernel(const float* __restrict__ Q,
                    const float* __restrict__ K,
                    const float* __restrict__ V,
                    float* __restrict__ O)
{
    extern __shared__ float sm[];
    uint32_t* Qs = (uint32_t*)(sm + AS_QS);
    uint32_t* Ks = (uint32_t*)(sm + AS_KS);
    uint32_t* Vs = (uint32_t*)(sm + AS_VS);
    float*    Ps = sm + AS_PS;
    uint32_t* Pu = (uint32_t*)Ps;
    float* mrow = sm + AS_M;
    float* lrow = sm + AS_L;
    float* srow = sm + AS_S;

    const int tid  = threadIdx.x;
    const int lane = tid & 31;
    const int warp = tid >> 5;      // 0..15
    const int g    = lane >> 2;
    const int tig  = lane & 3;
    const int wm   = warp >> 2;     // 0..3 -> q rows wm*32
    const int wn   = warp & 3;      // 0..3 -> kv slab (S) / d slab (PV)

    const int q0 = blockIdx.x * ABQ;
    const int h  = blockIdx.y;
    const int b  = blockIdx.z;
    const size_t base = (size_t)b * SEQ * HIDDEN + (size_t)h * HEADDIM;

    const float scale = 0.08838834764831845f;  // 1/sqrt(128)

    // ---- Load Q tile (128 x 128), scaled, tf32, natural layout ----
#pragma unroll
    for (int r = 0; r < 8; r++) {
        int q  = warp + 16 * r;
        int dg = lane * 4;
        float4 v = *(const float4*)(Q + base + (size_t)(q0 + q) * HIDDEN + dg);
        uint4 t = { f2tf32(v.x * scale), f2tf32(v.y * scale),
                    f2tf32(v.z * scale), f2tf32(v.w * scale) };
        *(uint4*)&Qs[q * LDQS + dg] = t;
    }
    if (tid < ABQ) { mrow[tid] = -INFINITY; lrow[tid] = 0.0f; }

    float o[2][4][4];
#pragma unroll
    for (int mi = 0; mi < 2; mi++)
#pragma unroll
        for (int nj = 0; nj < 4; nj++)
#pragma unroll
            for (int r = 0; r < 4; r++) o[mi][nj][r] = 0.0f;

    for (int kv0 = 0; kv0 < SEQ; kv0 += ABKV) {
        // ---- Load K (transposed+swizzled) and V (natural), tf32 ----
#pragma unroll
        for (int r = 0; r < 4; r++) {
            int kv = warp + 16 * r;
            int dg = lane * 4;
            float4 kq = *(const float4*)(K + base + (size_t)(kv0 + kv) * HIDDEN + dg);
            Ks[ks_idx(dg + 0, kv)] = f2tf32(kq.x);
            Ks[ks_idx(dg + 1, kv)] = f2tf32(kq.y);
            Ks[ks_idx(dg + 2, kv)] = f2tf32(kq.z);
            Ks[ks_idx(dg + 3, kv)] = f2tf32(kq.w);
            float4 vv = *(const float4*)(V + base + (size_t)(kv0 + kv) * HIDDEN + dg);
            uint4 u = { f2tf32(vv.x), f2tf32(vv.y), f2tf32(vv.z), f2tf32(vv.w) };
            *(uint4*)&Vs[kv * LDVS + dg] = u;
        }
        __syncthreads();

        // ---- S = Q @ K^T : warp tile 32x16 at (wm*32, wn*16) ----
        float sacc[2][2][4];
#pragma unroll
        for (int mi = 0; mi < 2; mi++)
#pragma unroll
            for (int ni = 0; ni < 2; ni++)
#pragma unroll
                for (int r = 0; r < 4; r++) sacc[mi][ni][r] = 0.0f;

#pragma unroll
        for (int ks = 0; ks < 16; ks++) {
            const int kk = ks * 8;
            uint32_t af[2][4], bf[2][2];
#pragma unroll
            for (int mi = 0; mi < 2; mi++) {
                int m = wm * 32 + mi * 16;
                af[mi][0] = Qs[(m + g) * LDQS + kk + tig];
                af[mi][1] = Qs[(m + g + 8) * LDQS + kk + tig];
                af[mi][2] = Qs[(m + g) * LDQS + kk + tig + 4];
                af[mi][3] = Qs[(m + g + 8) * LDQS + kk + tig + 4];
            }
#pragma unroll
            for (int ni = 0; ni < 2; ni++) {
                int n = wn * 16 + ni * 8;
                bf[ni][0] = Ks[ks_idx(kk + tig, n + g)];
                bf[ni][1] = Ks[ks_idx(kk + tig + 4, n + g)];
            }
#pragma unroll
            for (int mi = 0; mi < 2; mi++)
#pragma unroll
                for (int ni = 0; ni < 2; ni++)
                    mma_tf32(sacc[mi][ni], af[mi], bf[ni]);
        }
        // store scores
#pragma unroll
        for (int mi = 0; mi < 2; mi++) {
            int row = wm * 32 + mi * 16 + g;
#pragma unroll
            for (int ni = 0; ni < 2; ni++) {
                int col = wn * 16 + ni * 8 + tig * 2;
                float2 s0 = { sacc[mi][ni][0], sacc[mi][ni][1] };
                float2 s1 = { sacc[mi][ni][2], sacc[mi][ni][3] };
                *(float2*)&Ps[row * LDPS + col]       = s0;
                *(float2*)&Ps[(row + 8) * LDPS + col] = s1;
            }
        }
        __syncthreads();

        // ---- Online softmax: 4 threads per q-row ----
        {
            int r  = tid >> 2;
            int c0 = (tid & 3) * 16;
            float mloc = -INFINITY;
#pragma unroll 8
            for (int c = 0; c < 16; c++)
                mloc = fmaxf(mloc, Ps[r * LDPS + c0 + c]);
            mloc = fmaxf(mloc, __shfl_xor_sync(0xFFFFFFFF, mloc, 1));
            mloc = fmaxf(mloc, __shfl_xor_sync(0xFFFFFFFF, mloc, 2));
            float m_old = mrow[r];
            float m_new = fmaxf(m_old, mloc);
            float sc = __expf(m_old - m_new);
            float ls = 0.0f;
#pragma unroll 8
            for (int c = 0; c < 16; c++) {
                float p = __expf(Ps[r * LDPS + c0 + c] - m_new);
                uint32_t pb = f2tf32(p);
                Pu[r * LDPS + c0 + c] = pb;
                ls += __uint_as_float(pb);
            }
            ls += __shfl_xor_sync(0xFFFFFFFF, ls, 1);
            ls += __shfl_xor_sync(0xFFFFFFFF, ls, 2);
            if ((tid & 3) == 0) {
                mrow[r] = m_new;
                lrow[r] = lrow[r] * sc + ls;
                srow[r] = sc;
            }
        }
        __syncthreads();

        // ---- O rescale + O += P @ V : warp tile 32x32 at (wm*32, wn*32) ----
#pragma unroll
        for (int mi = 0; mi < 2; mi++) {
            int r0 = wm * 32 + mi * 16 + g;
            float s0 = srow[r0], s1 = srow[r0 + 8];
#pragma unroll
            for (int nj = 0; nj < 4; nj++) {
                o[mi][nj][0] *= s0; o[mi][nj][1] *= s0;
                o[mi][nj][2] *= s1; o[mi][nj][3] *= s1;
            }
        }
#pragma unroll
        for (int ks = 0; ks < 8; ks++) {
            const int kk = ks * 8;
            uint32_t af[2][4], bf[4][2];
#pragma unroll
            for (int mi = 0; mi < 2; mi++) {
                int m = wm * 32 + mi * 16;
                af[mi][0] = Pu[(m + g) * LDPS + kk + tig];
                af[mi][1] = Pu[(m + g + 8) * LDPS + kk + tig];
                af[mi][2] = Pu[(m + g) * LDPS + kk + tig + 4];
                af[mi][3] = Pu[(m + g + 8) * LDPS + kk + tig + 4];
            }
#pragma unroll
            for (int nj = 0; nj < 4; nj++) {
                int n = wn * 32 + nj * 8;
                bf[nj][0] = Vs[(kk + tig) * LDVS + n + g];
                bf[nj][1] = Vs[(kk + tig + 4) * LDVS + n + g];
            }
#pragma unroll
            for (int mi = 0; mi < 2; mi++)
#pragma unroll
                for (int nj = 0; nj < 4; nj++)
                    mma_tf32(o[mi][nj], af[mi], bf[nj]);
        }
        __syncthreads();
    }

    // ---- Epilogue: normalize by l, store ----
#pragma unroll
    for (int mi = 0; mi < 2; mi++) {
        int r0 = wm * 32 + mi * 16 + g;
        float inv0 = 1.0f / lrow[r0];
        float inv1 = 1.0f / lrow[r0 + 8];
#pragma unroll
        for (int nj = 0; nj < 4; nj++) {
            int col = wn * 32 + nj * 8 + tig * 2;
            float2 a = { o[mi][nj][0] * inv0, o[mi][nj][1] * inv0 };
            float2 c = { o[mi][nj][2] * inv1, o[mi][nj][3] * inv1 };
            *(float2*)(O + base + (size_t)(q0 + r0) * HIDDEN + col)     = a;
            *(float2*)(O + base + (size_t)(q0 + r0 + 8) * HIDDEN + col) = c;
        }
    }
}

// ---------------------------------------------------------------------------
// Launch
// ---------------------------------------------------------------------------
extern "C" void kernel_launch(void* const* d_in, const int* in_sizes, int n_in,
                              void* d_out, int out_size)
{
    (void)in_sizes; (void)n_in; (void)out_size;

    const float* hs = (const float*)d_in[0];
    const float* wq = (const float*)d_in[1];
    const float* bq = (const float*)d_in[2];
    const float* wk = (const float*)d_in[3];
    const float* bk = (const float*)d_in[4];
    const float* wv = (const float*)d_in[5];
    const float* bv = (const float*)d_in[6];
    const float* wo = (const float*)d_in[7];
    const float* bo = (const float*)d_in[8];
    float* out = (float*)d_out;

    float *q, *k, *v, *ao;
    cudaGetSymbolAddress((void**)&q,  g_q);
    cudaGetSymbolAddress((void**)&k,  g_k);
    cudaGetSymbolAddress((void**)&v,  g_v);
    cudaGetSymbolAddress((void**)&ao, g_ao);

    cudaFuncSetAttribute(attn_tc_kernel,
                         cudaFuncAttributeMaxDynamicSharedMemorySize,
                         (int)ATTN_SMEM_BYTES);

    dim3 gemm_grid(HIDDEN / GBN, MTOK / GBM);   // (16, 32)
    dim3 gemm_blk(256);

    gemm_tf32_kernel<<<gemm_grid, gemm_blk>>>(hs, wq, bq, q, MTOK, HIDDEN, HIDDEN);
    gemm_tf32_kernel<<<gemm_grid, gemm_blk>>>(hs, wk, bk, k, MTOK, HIDDEN, HIDDEN);
    gemm_tf32_kernel<<<gemm_grid, gemm_blk>>>(hs, wv, bv, v, MTOK, HIDDEN, HIDDEN);

    dim3 attn_grid(SEQ / ABQ, NHEADS, BATCH);   // (16, 16, 2)
    attn_tc_kernel<<<attn_grid, 512, ATTN_SMEM_BYTES>>>(q, k, v, ao);

    gemm_tf32_kernel<<<gemm_grid, gemm_blk>>>(ao, wo, bo, out, MTOK, HIDDEN, HIDDEN);
}

// round 7
// speedup vs baseline: 3.5667x; 1.0631x over previous
#include <cuda_runtime.h>
#include <math.h>
#include <stdint.h>

// Problem constants (fixed by the reference)
#define HIDDEN 2048
#define NHEADS 16
#define HEADDIM 128
#define BATCH 2
#define SEQ 2048
#define MTOK (BATCH * SEQ)   // 4096

// ---------------------------------------------------------------------------
// Scratch buffers (allocation-free rule: __device__ globals)
// ---------------------------------------------------------------------------
__device__ float g_q[MTOK * HIDDEN];
__device__ float g_k[MTOK * HIDDEN];
__device__ float g_v[MTOK * HIDDEN];
__device__ float g_ao[MTOK * HIDDEN];

__device__ __forceinline__ uint32_t f2tf32(float f) {
    uint32_t r;
    asm("cvt.rna.tf32.f32 %0, %1;" : "=r"(r) : "f"(f));
    return r;
}

__device__ __forceinline__ void mma_tf32(float* c, const uint32_t* a, const uint32_t* b) {
    asm volatile(
        "mma.sync.aligned.m16n8k8.row.col.f32.tf32.tf32.f32 "
        "{%0,%1,%2,%3}, {%4,%5,%6,%7}, {%8,%9}, {%0,%1,%2,%3};\n"
        : "+f"(c[0]), "+f"(c[1]), "+f"(c[2]), "+f"(c[3])
        : "r"(a[0]), "r"(a[1]), "r"(a[2]), "r"(a[3]), "r"(b[0]), "r"(b[1]));
}

// ---------------------------------------------------------------------------
// TF32 tensor-core GEMM: C[M,N] = A[M,K] @ W[K,N] + bias[N]
// 128x128x32 tile, 256 threads, 2 CTAs/SM.
// ---------------------------------------------------------------------------
#define GBM 128
#define GBN 128
#define GBK 32

__global__ __launch_bounds__(256, 2)
void gemm_tf32_kernel(const float* __restrict__ A,
                      const float* __restrict__ W,
                      const float* __restrict__ bias,
                      float* __restrict__ C,
                      int M, int N, int K)
{
    __shared__ uint32_t As[GBM][GBK + 4];
    __shared__ uint32_t Bs[GBK][GBN + 8];

    const int tid  = threadIdx.x;
    const int lane = tid & 31;
    const int warp = tid >> 5;
    const int wm   = warp >> 2;
    const int wn   = warp & 3;
    const int g    = lane >> 2;
    const int tig  = lane & 3;

    const int bm = blockIdx.y * GBM;
    const int bn = blockIdx.x * GBN;

    const int a_r0 = tid >> 3;
    const int a_c  = (tid & 7) * 4;
    const int b_r0 = tid >> 5;
    const int b_c  = (tid & 31) * 4;

    float acc[4][4][4];
#pragma unroll
    for (int mi = 0; mi < 4; mi++)
#pragma unroll
        for (int ni = 0; ni < 4; ni++)
#pragma unroll
            for (int r = 0; r < 4; r++) acc[mi][ni][r] = 0.0f;

    const int nk = K / GBK;

#pragma unroll
    for (int i = 0; i < 4; i++) {
        int ar = a_r0 + 32 * i;
        float4 v = *(const float4*)(A + (size_t)(bm + ar) * K + a_c);
        uint4 t = { f2tf32(v.x), f2tf32(v.y), f2tf32(v.z), f2tf32(v.w) };
        *(uint4*)&As[ar][a_c] = t;

        int br = b_r0 + 8 * i;
        float4 w = *(const float4*)(W + (size_t)br * N + bn + b_c);
        uint4 u = { f2tf32(w.x), f2tf32(w.y), f2tf32(w.z), f2tf32(w.w) };
        *(uint4*)&Bs[br][b_c] = u;
    }
    __syncthreads();

    for (int kt = 0; kt < nk; kt++) {
        float4 pa[4], pb[4];
        if (kt + 1 < nk) {
            int k0 = (kt + 1) * GBK;
#pragma unroll
            for (int i = 0; i < 4; i++) {
                int ar = a_r0 + 32 * i;
                pa[i] = *(const float4*)(A + (size_t)(bm + ar) * K + k0 + a_c);
                int br = b_r0 + 8 * i;
                pb[i] = *(const float4*)(W + (size_t)(k0 + br) * N + bn + b_c);
            }
        }

#pragma unroll
        for (int ks = 0; ks < 4; ks++) {
            const int kk = ks * 8;
            uint32_t af[4][4], bf[4][2];
#pragma unroll
            for (int mi = 0; mi < 4; mi++) {
                int m = wm * 64 + mi * 16;
                af[mi][0] = As[m + g][kk + tig];
                af[mi][1] = As[m + g + 8][kk + tig];
                af[mi][2] = As[m + g][kk + tig + 4];
                af[mi][3] = As[m + g + 8][kk + tig + 4];
            }
#pragma unroll
            for (int ni = 0; ni < 4; ni++) {
                int n = wn * 32 + ni * 8;
                bf[ni][0] = Bs[kk + tig][n + g];
                bf[ni][1] = Bs[kk + tig + 4][n + g];
            }
#pragma unroll
            for (int mi = 0; mi < 4; mi++)
#pragma unroll
                for (int ni = 0; ni < 4; ni++)
                    mma_tf32(acc[mi][ni], af[mi], bf[ni]);
        }
        __syncthreads();

        if (kt + 1 < nk) {
#pragma unroll
            for (int i = 0; i < 4; i++) {
                int ar = a_r0 + 32 * i;
                uint4 t = { f2tf32(pa[i].x), f2tf32(pa[i].y), f2tf32(pa[i].z), f2tf32(pa[i].w) };
                *(uint4*)&As[ar][a_c] = t;
                int br = b_r0 + 8 * i;
                uint4 u = { f2tf32(pb[i].x), f2tf32(pb[i].y), f2tf32(pb[i].z), f2tf32(pb[i].w) };
                *(uint4*)&Bs[br][b_c] = u;
            }
            __syncthreads();
        }
    }

#pragma unroll
    for (int ni = 0; ni < 4; ni++) {
        int col = bn + wn * 32 + ni * 8 + tig * 2;
        float b0 = bias[col], b1 = bias[col + 1];
#pragma unroll
        for (int mi = 0; mi < 4; mi++) {
            int row = bm + wm * 64 + mi * 16 + g;
            float2 r0 = { acc[mi][ni][0] + b0, acc[mi][ni][1] + b1 };
            float2 r1 = { acc[mi][ni][2] + b0, acc[mi][ni][3] + b1 };
            *(float2*)(C + (size_t)row * N + col)       = r0;
            *(float2*)(C + (size_t)(row + 8) * N + col) = r1;
        }
    }
}

// ---------------------------------------------------------------------------
// Tensor-core flash attention, 256 threads (8 warps), BQ=128, BKV=64.
// S-phase: warp grid 4x2, tile 32x32.  PV: warp grid 4x2, tile 32x64.
// Softmax fused in registers: m/l state in registers, scores never re-read.
// ---------------------------------------------------------------------------
#define ABQ 128
#define ABKV 64
#define LDQS 132   // Qs [128 q][d] stride  -> a-frag reads conflict-free
#define LDVS 136   // Vs [64 kv][d] stride  -> b-frag reads conflict-free
#define LDPS 66    // Ps [128 q][kv] stride -> even (8B-aligned uint2 stores)

// Ks swizzled [d][kv]: conflict-free transposed scalar stores AND b-frag reads
__device__ __forceinline__ int ks_idx(int d, int kv) {
    int x = ((d & 3) << 3) ^ ((d >> 2) & 31);
    return d * 64 + (kv ^ x);
}

#define AS_QS 0
#define AS_KS (AS_QS + ABQ * LDQS)            // 16896
#define AS_VS (AS_KS + HEADDIM * 64)          // + 8192
#define AS_PS (AS_VS + ABKV * LDVS)           // + 8704
#define AS_MB (AS_PS + ABQ * LDPS)            // + 8448   maxbuf[2][128]
#define AS_LB (AS_MB + 2 * ABQ)               //          lbuf[2][128]
#define AS_TOT (AS_LB + 2 * ABQ)
#define ATTN_SMEM_BYTES (AS_TOT * sizeof(float))   // ~171 KB

__global__ __launch_bounds__(256)
void attn_tc_kernel(const float* __restrict__ Q,
                    const float* __restrict__ K,
                    const float* __restrict__ V,
                    float* __restrict__ O)
{
    extern __shared__ float sm[];
    uint32_t* Qs = (uint32_t*)(sm + AS_QS);
    uint32_t* Ks = (uint32_t*)(sm + AS_KS);
    uint32_t* Vs = (uint32_t*)(sm + AS_VS);
    uint32_t* Pu = (uint32_t*)(sm + AS_PS);
    float* maxbuf = sm + AS_MB;   // [2][128]
    float* lbuf   = sm + AS_LB;   // [2][128]

    const int tid  = threadIdx.x;
    const int lane = tid & 31;
    const int warp = tid >> 5;
    const int g    = lane >> 2;
    const int tig  = lane & 3;
    const int wm   = warp >> 1;    // 0..3 -> q rows wm*32
    const int wn   = warp & 1;     // 0..1 -> kv slab (S) / d slab (PV)

    const int q0 = blockIdx.x * ABQ;
    const int h  = blockIdx.y;
    const int b  = blockIdx.z;
    const size_t base = (size_t)b * SEQ * HIDDEN + (size_t)h * HEADDIM;

    const float scale = 0.08838834764831845f;  // 1/sqrt(128)

    // Rows owned by this thread (fixed for the whole kernel):
    // i = mi*2 + h : row = wm*32 + mi*16 + h*8 + g
    const int rowA0 = wm * 32 + g;         // mi=0, low
    // per-row online-softmax state in registers
    float mreg[4] = { -INFINITY, -INFINITY, -INFINITY, -INFINITY };
    float lreg[4] = { 0.0f, 0.0f, 0.0f, 0.0f };

    // ---- Load Q tile (128 x 128), scaled, tf32, natural layout ----
#pragma unroll
    for (int r = 0; r < 16; r++) {
        int q  = (tid >> 5) + 8 * r;
        int dg = lane * 4;
        float4 v = *(const float4*)(Q + base + (size_t)(q0 + q) * HIDDEN + dg);
        uint4 t = { f2tf32(v.x * scale), f2tf32(v.y * scale),
                    f2tf32(v.z * scale), f2tf32(v.w * scale) };
        *(uint4*)&Qs[q * LDQS + dg] = t;
    }

    float o[2][8][4];
#pragma unroll
    for (int mi = 0; mi < 2; mi++)
#pragma unroll
        for (int nj = 0; nj < 8; nj++)
#pragma unroll
            for (int r = 0; r < 4; r++) o[mi][nj][r] = 0.0f;

    for (int kv0 = 0; kv0 < SEQ; kv0 += ABKV) {
        // ---- Load K (transposed+swizzled) and V (natural), tf32 ----
#pragma unroll
        for (int r = 0; r < 8; r++) {
            int kv = (tid >> 5) + 8 * r;
            int dg = lane * 4;
            float4 kq = *(const float4*)(K + base + (size_t)(kv0 + kv) * HIDDEN + dg);
            Ks[ks_idx(dg + 0, kv)] = f2tf32(kq.x);
            Ks[ks_idx(dg + 1, kv)] = f2tf32(kq.y);
            Ks[ks_idx(dg + 2, kv)] = f2tf32(kq.z);
            Ks[ks_idx(dg + 3, kv)] = f2tf32(kq.w);
            float4 vv = *(const float4*)(V + base + (size_t)(kv0 + kv) * HIDDEN + dg);
            uint4 u = { f2tf32(vv.x), f2tf32(vv.y), f2tf32(vv.z), f2tf32(vv.w) };
            *(uint4*)&Vs[kv * LDVS + dg] = u;
        }
        __syncthreads();

        // ---- S = Q @ K^T : warp tile 32x32 at (wm*32, wn*32) ----
        float sacc[2][4][4];
#pragma unroll
        for (int mi = 0; mi < 2; mi++)
#pragma unroll
            for (int ni = 0; ni < 4; ni++)
#pragma unroll
                for (int r = 0; r < 4; r++) sacc[mi][ni][r] = 0.0f;

#pragma unroll
        for (int ks = 0; ks < 16; ks++) {
            const int kk = ks * 8;
            uint32_t af[2][4], bf[4][2];
#pragma unroll
            for (int mi = 0; mi < 2; mi++) {
                int m = wm * 32 + mi * 16;
                af[mi][0] = Qs[(m + g) * LDQS + kk + tig];
                af[mi][1] = Qs[(m + g + 8) * LDQS + kk + tig];
                af[mi][2] = Qs[(m + g) * LDQS + kk + tig + 4];
                af[mi][3] = Qs[(m + g + 8) * LDQS + kk + tig + 4];
            }
#pragma unroll
            for (int ni = 0; ni < 4; ni++) {
                int n = wn * 32 + ni * 8;
                bf[ni][0] = Ks[ks_idx(kk + tig, n + g)];
                bf[ni][1] = Ks[ks_idx(kk + tig + 4, n + g)];
            }
#pragma unroll
            for (int mi = 0; mi < 2; mi++)
#pragma unroll
                for (int ni = 0; ni < 4; ni++)
                    mma_tf32(sacc[mi][ni], af[mi], bf[ni]);
        }

        // ---- Fused softmax part 1: warp-local row maxes (registers) ----
#pragma unroll
        for (int mi = 0; mi < 2; mi++) {
            float a = -INFINITY, c = -INFINITY;
#pragma unroll
            for (int ni = 0; ni < 4; ni++) {
                a = fmaxf(a, fmaxf(sacc[mi][ni][0], sacc[mi][ni][1]));
                c = fmaxf(c, fmaxf(sacc[mi][ni][2], sacc[mi][ni][3]));
            }
            a = fmaxf(a, __shfl_xor_sync(0xFFFFFFFF, a, 1));
            a = fmaxf(a, __shfl_xor_sync(0xFFFFFFFF, a, 2));
            c = fmaxf(c, __shfl_xor_sync(0xFFFFFFFF, c, 1));
            c = fmaxf(c, __shfl_xor_sync(0xFFFFFFFF, c, 2));
            if (tig == 0) {
                maxbuf[wn * ABQ + rowA0 + mi * 16]     = a;
                maxbuf[wn * ABQ + rowA0 + mi * 16 + 8] = c;
            }
        }
        __syncthreads();

        // ---- Fused softmax part 2: combine maxes, exp in regs, write P ----
        float sc[4], lsum[4];
#pragma unroll
        for (int i = 0; i < 4; i++) {
            int row = rowA0 + (i >> 1) * 16 + (i & 1) * 8;
            float mn = fmaxf(mreg[i], fmaxf(maxbuf[row], maxbuf[ABQ + row]));
            sc[i] = __expf(mreg[i] - mn);
            mreg[i] = mn;
            lsum[i] = 0.0f;
        }
#pragma unroll
        for (int mi = 0; mi < 2; mi++) {
            int rA = rowA0 + mi * 16;
#pragma unroll
            for (int ni = 0; ni < 4; ni++) {
                int col = wn * 32 + ni * 8 + tig * 2;
                uint32_t p0 = f2tf32(__expf(sacc[mi][ni][0] - mreg[mi * 2]));
                uint32_t p1 = f2tf32(__expf(sacc[mi][ni][1] - mreg[mi * 2]));
                uint32_t p2 = f2tf32(__expf(sacc[mi][ni][2] - mreg[mi * 2 + 1]));
                uint32_t p3 = f2tf32(__expf(sacc[mi][ni][3] - mreg[mi * 2 + 1]));
                lsum[mi * 2]     += __uint_as_float(p0) + __uint_as_float(p1);
                lsum[mi * 2 + 1] += __uint_as_float(p2) + __uint_as_float(p3);
                uint2 w0 = { p0, p1 };
                uint2 w1 = { p2, p3 };
                *(uint2*)&Pu[rA * LDPS + col]       = w0;
                *(uint2*)&Pu[(rA + 8) * LDPS + col] = w1;
            }
        }
#pragma unroll
        for (int i = 0; i < 4; i++) {
            float ls = lsum[i];
            ls += __shfl_xor_sync(0xFFFFFFFF, ls, 1);
            ls += __shfl_xor_sync(0xFFFFFFFF, ls, 2);
            lsum[i] = ls;
        }
        if (tig == 0) {
#pragma unroll
            for (int i = 0; i < 4; i++) {
                int row = rowA0 + (i >> 1) * 16 + (i & 1) * 8;
                lbuf[wn * ABQ + row] = lsum[i];
            }
        }
        __syncthreads();

#pragma unroll
        for (int i = 0; i < 4; i++) {
            int row = rowA0 + (i >> 1) * 16 + (i & 1) * 8;
            lreg[i] = lreg[i] * sc[i] + lbuf[row] + lbuf[ABQ + row];
        }

        // ---- O rescale + O += P @ V : warp tile 32x64 at (wm*32, wn*64) ----
#pragma unroll
        for (int mi = 0; mi < 2; mi++) {
            float s0 = sc[mi * 2], s1 = sc[mi * 2 + 1];
#pragma unroll
            for (int nj = 0; nj < 8; nj++) {
                o[mi][nj][0] *= s0; o[mi][nj][1] *= s0;
                o[mi][nj][2] *= s1; o[mi][nj][3] *= s1;
            }
        }
#pragma unroll
        for (int ks = 0; ks < 8; ks++) {
            const int kk = ks * 8;
            uint32_t af[2][4], bf[8][2];
#pragma unroll
            for (int mi = 0; mi < 2; mi++) {
                int m = wm * 32 + mi * 16;
                af[mi][0] = Pu[(m + g) * LDPS + kk + tig];
                af[mi][1] = Pu[(m + g + 8) * LDPS + kk + tig];
                af[mi][2] = Pu[(m + g) * LDPS + kk + tig + 4];
                af[mi][3] = Pu[(m + g + 8) * LDPS + kk + tig + 4];
            }
#pragma unroll
            for (int nj = 0; nj < 8; nj++) {
                int n = wn * 64 + nj * 8;
                bf[nj][0] = Vs[(kk + tig) * LDVS + n + g];
                bf[nj][1] = Vs[(kk + tig + 4) * LDVS + n + g];
            }
#pragma unroll
            for (int mi = 0; mi < 2; mi++)
#pragma unroll
                for (int nj = 0; nj < 8; nj++)
                    mma_tf32(o[mi][nj], af[mi], bf[nj]);
        }
        __syncthreads();
    }

    // ---- Epilogue: normalize by l (registers), store ----
#pragma unroll
    for (int mi = 0; mi < 2; mi++) {
        int r0 = wm * 32 + mi * 16 + g;
        float inv0 = 1.0f / lreg[mi * 2];
        float inv1 = 1.0f / lreg[mi * 2 + 1];
#pragma unroll
        for (int nj = 0; nj < 8; nj++) {
            int col = wn * 64 + nj * 8 + tig * 2;
            float2 a = { o[mi][nj][0] * inv0, o[mi][nj][1] * inv0 };
            float2 c = { o[mi][nj][2] * inv1, o[mi][nj][3] * inv1 };
            *(float2*)(O + base + (size_t)(q0 + r0) * HIDDEN + col)     = a;
            *(float2*)(O + base + (size_t)(q0 + r0 + 8) * HIDDEN + col) = c;
        }
    }
}

// ---------------------------------------------------------------------------
// Launch
// ---------------------------------------------------------------------------
extern "C" void kernel_launch(void* const* d_in, const int* in_sizes, int n_in,
                              void* d_out, int out_size)
{
    (void)in_sizes; (void)n_in; (void)out_size;

    const float* hs = (const float*)d_in[0];
    const float* wq = (const float*)d_in[1];
    const float* bq = (const float*)d_in[2];
    const float* wk = (const float*)d_in[3];
    const float* bk = (const float*)d_in[4];
    const float* wv = (const float*)d_in[5];
    const float* bv = (const float*)d_in[6];
    const float* wo = (const float*)d_in[7];
    const float* bo = (const float*)d_in[8];
    float* out = (float*)d_out;

    float *q, *k, *v, *ao;
    cudaGetSymbolAddress((void**)&q,  g_q);
    cudaGetSymbolAddress((void**)&k,  g_k);
    cudaGetSymbolAddress((void**)&v,  g_v);
    cudaGetSymbolAddress((void**)&ao, g_ao);

    cudaFuncSetAttribute(attn_tc_kernel,
                         cudaFuncAttributeMaxDynamicSharedMemorySize,
                         (int)ATTN_SMEM_BYTES);

    dim3 gemm_grid(HIDDEN / GBN, MTOK / GBM);   // (16, 32)
    dim3 gemm_blk(256);

    gemm_tf32_kernel<<<gemm_grid, gemm_blk>>>(hs, wq, bq, q, MTOK, HIDDEN, HIDDEN);
    gemm_tf32_kernel<<<gemm_grid, gemm_blk>>>(hs, wk, bk, k, MTOK, HIDDEN, HIDDEN);
    gemm_tf32_kernel<<<gemm_grid, gemm_blk>>>(hs, wv, bv, v, MTOK, HIDDEN, HIDDEN);

    dim3 attn_grid(SEQ / ABQ, NHEADS, BATCH);   // (16, 16, 2)
    attn_tc_kernel<<<attn_grid, 256, ATTN_SMEM_BYTES>>>(q, k, v, ao);

    gemm_tf32_kernel<<<gemm_grid, gemm_blk>>>(ao, wo, bo, out, MTOK, HIDDEN, HIDDEN);
}

// round 8
// speedup vs baseline: 4.2514x; 1.1920x over previous
#include <cuda_runtime.h>
#include <math.h>
#include <stdint.h>

// Problem constants (fixed by the reference)
#define HIDDEN 2048
#define NHEADS 16
#define HEADDIM 128
#define BATCH 2
#define SEQ 2048
#define MTOK (BATCH * SEQ)   // 4096

// ---------------------------------------------------------------------------
// Scratch buffers (allocation-free rule: __device__ globals)
// ---------------------------------------------------------------------------
__device__ float g_q[MTOK * HIDDEN];
__device__ float g_k[MTOK * HIDDEN];
__device__ float g_v[MTOK * HIDDEN];
__device__ float g_ao[MTOK * HIDDEN];
__device__ float g_hs[MTOK * HIDDEN];        // tf32-rounded hidden states
__device__ float g_wq[HIDDEN * HIDDEN];      // tf32(scale * wq)
__device__ float g_wk[HIDDEN * HIDDEN];
__device__ float g_wv[HIDDEN * HIDDEN];
__device__ float g_wo[HIDDEN * HIDDEN];
__device__ float g_bqs[HIDDEN];              // scale * bq

__device__ __forceinline__ uint32_t f2tf32(float f) {
    uint32_t r;
    asm("cvt.rna.tf32.f32 %0, %1;" : "=r"(r) : "f"(f));
    return r;
}

__device__ __forceinline__ void mma_tf32(float* c, const uint32_t* a, const uint32_t* b) {
    asm volatile(
        "mma.sync.aligned.m16n8k8.row.col.f32.tf32.tf32.f32 "
        "{%0,%1,%2,%3}, {%4,%5,%6,%7}, {%8,%9}, {%0,%1,%2,%3};\n"
        : "+f"(c[0]), "+f"(c[1]), "+f"(c[2]), "+f"(c[3])
        : "r"(a[0]), "r"(a[1]), "r"(a[2]), "r"(a[3]), "r"(b[0]), "r"(b[1]));
}

__device__ __forceinline__ void cp_async16(uint32_t smem_addr, const void* gptr) {
    asm volatile("cp.async.cg.shared.global [%0], [%1], 16;"
                 :: "r"(smem_addr), "l"(gptr));
}
#define CP_COMMIT() asm volatile("cp.async.commit_group;" ::: "memory")
#define CP_WAIT(N)  asm volatile("cp.async.wait_group %0;" :: "n"(N) : "memory")

// ---------------------------------------------------------------------------
// Prep: round to tf32 (optionally scaled) once per launch
// ---------------------------------------------------------------------------
__global__ void prep_round_kernel(const float* __restrict__ src,
                                  float* __restrict__ dst,
                                  float mul, int n4)
{
    int i = blockIdx.x * blockDim.x + threadIdx.x;
    if (i < n4) {
        float4 v = *(const float4*)(src + i * 4);
        float4 o;
        o.x = __uint_as_float(f2tf32(v.x * mul));
        o.y = __uint_as_float(f2tf32(v.y * mul));
        o.z = __uint_as_float(f2tf32(v.z * mul));
        o.w = __uint_as_float(f2tf32(v.w * mul));
        *(float4*)(dst + i * 4) = o;
    }
}

// ---------------------------------------------------------------------------
// TF32 tensor-core GEMM: C = A[M,K] @ W[K,N] + bias ; A,W pre-rounded tf32.
// 128x128x32 tile, 256 threads, 2 CTAs/SM, 2-stage cp.async pipeline.
// ---------------------------------------------------------------------------
#define GBM 128
#define GBN 128
#define GBK 32
#define ALD 36    // As row stride (words): 4g+tig conflict-free
#define BLD 136   // Bs row stride (words): 8tig+g conflict-free
#define GEMM_STAGE_A (GBM * ALD)     // 4608 words
#define GEMM_STAGE_B (GBK * BLD)     // 4352 words
#define GEMM_SMEM_WORDS (2 * GEMM_STAGE_A + 2 * GEMM_STAGE_B)
#define GEMM_SMEM_BYTES (GEMM_SMEM_WORDS * 4)   // 71680

__global__ __launch_bounds__(256, 2)
void gemm_tf32_kernel(const float* __restrict__ A,
                      const float* __restrict__ W,
                      const float* __restrict__ bias,
                      float* __restrict__ C,
                      int round_out)
{
    extern __shared__ uint32_t gsm[];
    uint32_t* Asm = gsm;                       // [2][GBM][ALD]
    uint32_t* Bsm = gsm + 2 * GEMM_STAGE_A;    // [2][GBK][BLD]
    const uint32_t as_u32 = (uint32_t)__cvta_generic_to_shared(Asm);
    const uint32_t bs_u32 = (uint32_t)__cvta_generic_to_shared(Bsm);

    const int tid  = threadIdx.x;
    const int lane = tid & 31;
    const int warp = tid >> 5;
    const int wm   = warp >> 2;
    const int wn   = warp & 3;
    const int g    = lane >> 2;
    const int tig  = lane & 3;

    const int bm = blockIdx.y * GBM;
    const int bn = blockIdx.x * GBN;
    const int K = HIDDEN, N = HIDDEN;

    const int a_r0 = tid >> 3;        // 0..31 (+32i)
    const int a_c  = (tid & 7) * 4;
    const int b_r0 = tid >> 5;        // 0..7  (+8i)
    const int b_c  = (tid & 31) * 4;

    float acc[4][4][4];
#pragma unroll
    for (int mi = 0; mi < 4; mi++)
#pragma unroll
        for (int ni = 0; ni < 4; ni++)
#pragma unroll
            for (int r = 0; r < 4; r++) acc[mi][ni][r] = 0.0f;

    const int nk = K / GBK;   // 64

    // ---- prologue: tile 0 -> stage 0 ----
#pragma unroll
    for (int i = 0; i < 4; i++) {
        int ar = a_r0 + 32 * i;
        cp_async16(as_u32 + (ar * ALD + a_c) * 4,
                   A + (size_t)(bm + ar) * K + a_c);
        int br = b_r0 + 8 * i;
        cp_async16(bs_u32 + (br * BLD + b_c) * 4,
                   W + (size_t)br * N + bn + b_c);
    }
    CP_COMMIT();

    for (int kt = 0; kt < nk; kt++) {
        const int cur = kt & 1;
        if (kt + 1 < nk) {
            const int nxt = (kt + 1) & 1;
            const int k0 = (kt + 1) * GBK;
#pragma unroll
            for (int i = 0; i < 4; i++) {
                int ar = a_r0 + 32 * i;
                cp_async16(as_u32 + (nxt * GEMM_STAGE_A + ar * ALD + a_c) * 4,
                           A + (size_t)(bm + ar) * K + k0 + a_c);
                int br = b_r0 + 8 * i;
                cp_async16(bs_u32 + (nxt * GEMM_STAGE_B + br * BLD + b_c) * 4,
                           W + (size_t)(k0 + br) * N + bn + b_c);
            }
            CP_COMMIT();
            CP_WAIT(1);
        } else {
            CP_WAIT(0);
        }
        __syncthreads();

        const uint32_t* As = Asm + cur * GEMM_STAGE_A;
        const uint32_t* Bs = Bsm + cur * GEMM_STAGE_B;
#pragma unroll
        for (int ks = 0; ks < 4; ks++) {
            const int kk = ks * 8;
            uint32_t af[4][4], bf[4][2];
#pragma unroll
            for (int mi = 0; mi < 4; mi++) {
                int m = wm * 64 + mi * 16;
                af[mi][0] = As[(m + g) * ALD + kk + tig];
                af[mi][1] = As[(m + g + 8) * ALD + kk + tig];
                af[mi][2] = As[(m + g) * ALD + kk + tig + 4];
                af[mi][3] = As[(m + g + 8) * ALD + kk + tig + 4];
            }
#pragma unroll
            for (int ni = 0; ni < 4; ni++) {
                int n = wn * 32 + ni * 8;
                bf[ni][0] = Bs[(kk + tig) * BLD + n + g];
                bf[ni][1] = Bs[(kk + tig + 4) * BLD + n + g];
            }
#pragma unroll
            for (int mi = 0; mi < 4; mi++)
#pragma unroll
                for (int ni = 0; ni < 4; ni++)
                    mma_tf32(acc[mi][ni], af[mi], bf[ni]);
        }
        __syncthreads();
    }

    // ---- epilogue ----
#pragma unroll
    for (int ni = 0; ni < 4; ni++) {
        int col = bn + wn * 32 + ni * 8 + tig * 2;
        float b0 = bias[col], b1 = bias[col + 1];
#pragma unroll
        for (int mi = 0; mi < 4; mi++) {
            int row = bm + wm * 64 + mi * 16 + g;
            float v00 = acc[mi][ni][0] + b0, v01 = acc[mi][ni][1] + b1;
            float v10 = acc[mi][ni][2] + b0, v11 = acc[mi][ni][3] + b1;
            if (round_out) {
                v00 = __uint_as_float(f2tf32(v00));
                v01 = __uint_as_float(f2tf32(v01));
                v10 = __uint_as_float(f2tf32(v10));
                v11 = __uint_as_float(f2tf32(v11));
            }
            float2 r0 = { v00, v01 };
            float2 r1 = { v10, v11 };
            *(float2*)(C + (size_t)row * HIDDEN + col)       = r0;
            *(float2*)(C + (size_t)(row + 8) * HIDDEN + col) = r1;
        }
    }
}

// ---------------------------------------------------------------------------
// Tensor-core flash attention, 256 threads, BQ=128, BKV=64.
// Q/K/V pre-rounded tf32 (Q pre-scaled). All loads via cp.async; K(t+1)
// overlaps softmax+PV, V(t+1) overlaps next S-phase. Softmax fused in regs.
// ---------------------------------------------------------------------------
#define ABQ 128
#define ABKV 64
#define LDQS 132   // Qs [q][d]  : a-frags 4g+tig conflict-free
#define LDKS 132   // Ks [kv][d] : b-frags 4g+tig conflict-free (row-major!)
#define LDVS 136   // Vs [kv][d] : b-frags 8tig+g conflict-free
#define LDPS 66    // Ps [q][kv] : even (8B-aligned uint2 stores)

#define AS_QS 0
#define AS_KS (AS_QS + ABQ * LDQS)        // 16896
#define AS_VS (AS_KS + ABKV * LDKS)       // 25344
#define AS_PS (AS_VS + ABKV * LDVS)       // 34048
#define AS_MB (AS_PS + ABQ * LDPS)        // 42496
#define AS_LB (AS_MB + 2 * ABQ)           // 42752
#define AS_TOT (AS_LB + 2 * ABQ)          // 43008 words
#define ATTN_SMEM_BYTES (AS_TOT * 4)      // 172032 B

__global__ __launch_bounds__(256)
void attn_tc_kernel(const float* __restrict__ Q,
                    const float* __restrict__ K,
                    const float* __restrict__ V,
                    float* __restrict__ O)
{
    extern __shared__ float sm[];
    uint32_t* Qs = (uint32_t*)(sm + AS_QS);
    uint32_t* Ks = (uint32_t*)(sm + AS_KS);
    uint32_t* Vs = (uint32_t*)(sm + AS_VS);
    uint32_t* Pu = (uint32_t*)(sm + AS_PS);
    float* maxbuf = sm + AS_MB;
    float* lbuf   = sm + AS_LB;
    const uint32_t qs_u32 = (uint32_t)__cvta_generic_to_shared(Qs);
    const uint32_t ks_u32 = (uint32_t)__cvta_generic_to_shared(Ks);
    const uint32_t vs_u32 = (uint32_t)__cvta_generic_to_shared(Vs);

    const int tid  = threadIdx.x;
    const int lane = tid & 31;
    const int warp = tid >> 5;
    const int g    = lane >> 2;
    const int tig  = lane & 3;
    const int wm   = warp >> 1;
    const int wn   = warp & 1;

    const int q0 = blockIdx.x * ABQ;
    const int h  = blockIdx.y;
    const int b  = blockIdx.z;
    const size_t base = (size_t)b * SEQ * HIDDEN + (size_t)h * HEADDIM;

    const int rowA0 = wm * 32 + g;
    float mreg[4] = { -INFINITY, -INFINITY, -INFINITY, -INFINITY };
    float lreg[4] = { 0.0f, 0.0f, 0.0f, 0.0f };

    const int ldr = tid >> 5;      // row group for async loads
    const int dg  = lane * 4;      // 16B column chunk

    // ---- prologue: Q tile, then K(0), V(0) ----
#pragma unroll
    for (int r = 0; r < 16; r++) {
        int q = ldr + 8 * r;
        cp_async16(qs_u32 + (q * LDQS + dg) * 4,
                   Q + base + (size_t)(q0 + q) * HIDDEN + dg);
    }
    CP_COMMIT();
#pragma unroll
    for (int r = 0; r < 8; r++) {
        int kv = ldr + 8 * r;
        cp_async16(ks_u32 + (kv * LDKS + dg) * 4,
                   K + base + (size_t)kv * HIDDEN + dg);
    }
    CP_COMMIT();
#pragma unroll
    for (int r = 0; r < 8; r++) {
        int kv = ldr + 8 * r;
        cp_async16(vs_u32 + (kv * LDVS + dg) * 4,
                   V + base + (size_t)kv * HIDDEN + dg);
    }
    CP_COMMIT();

    float o[2][8][4];
#pragma unroll
    for (int mi = 0; mi < 2; mi++)
#pragma unroll
        for (int nj = 0; nj < 8; nj++)
#pragma unroll
            for (int r = 0; r < 4; r++) o[mi][nj][r] = 0.0f;

    const int NT = SEQ / ABKV;    // 32
    for (int t = 0; t < NT; t++) {
        // K(t) (and Q on t=0) ready; V(t) may still be in flight
        CP_WAIT(1);
        __syncthreads();

        // ---- S = Q @ K^T : warp tile 32x32 ----
        float sacc[2][4][4];
#pragma unroll
        for (int mi = 0; mi < 2; mi++)
#pragma unroll
            for (int ni = 0; ni < 4; ni++)
#pragma unroll
                for (int r = 0; r < 4; r++) sacc[mi][ni][r] = 0.0f;

#pragma unroll
        for (int ks = 0; ks < 16; ks++) {
            const int kk = ks * 8;
            uint32_t af[2][4], bf[4][2];
#pragma unroll
            for (int mi = 0; mi < 2; mi++) {
                int m = wm * 32 + mi * 16;
                af[mi][0] = Qs[(m + g) * LDQS + kk + tig];
                af[mi][1] = Qs[(m + g + 8) * LDQS + kk + tig];
                af[mi][2] = Qs[(m + g) * LDQS + kk + tig + 4];
                af[mi][3] = Qs[(m + g + 8) * LDQS + kk + tig + 4];
            }
#pragma unroll
            for (int ni = 0; ni < 4; ni++) {
                int n = wn * 32 + ni * 8;
                bf[ni][0] = Ks[(n + g) * LDKS + kk + tig];
                bf[ni][1] = Ks[(n + g) * LDKS + kk + tig + 4];
            }
#pragma unroll
            for (int mi = 0; mi < 2; mi++)
#pragma unroll
                for (int ni = 0; ni < 4; ni++)
                    mma_tf32(sacc[mi][ni], af[mi], bf[ni]);
        }

        // ---- warp-local row maxes ----
#pragma unroll
        for (int mi = 0; mi < 2; mi++) {
            float a = -INFINITY, c = -INFINITY;
#pragma unroll
            for (int ni = 0; ni < 4; ni++) {
                a = fmaxf(a, fmaxf(sacc[mi][ni][0], sacc[mi][ni][1]));
                c = fmaxf(c, fmaxf(sacc[mi][ni][2], sacc[mi][ni][3]));
            }
            a = fmaxf(a, __shfl_xor_sync(0xFFFFFFFF, a, 1));
            a = fmaxf(a, __shfl_xor_sync(0xFFFFFFFF, a, 2));
            c = fmaxf(c, __shfl_xor_sync(0xFFFFFFFF, c, 1));
            c = fmaxf(c, __shfl_xor_sync(0xFFFFFFFF, c, 2));
            if (tig == 0) {
                maxbuf[wn * ABQ + rowA0 + mi * 16]     = a;
                maxbuf[wn * ABQ + rowA0 + mi * 16 + 8] = c;
            }
        }
        __syncthreads();   // Ks consumed + maxbuf visible

        // ---- prefetch K(t+1) (overlaps softmax + PV) ----
        if (t + 1 < NT) {
            const float* Kn = K + base + (size_t)(t + 1) * ABKV * HIDDEN;
#pragma unroll
            for (int r = 0; r < 8; r++) {
                int kv = ldr + 8 * r;
                cp_async16(ks_u32 + (kv * LDKS + dg) * 4,
                           Kn + (size_t)kv * HIDDEN + dg);
            }
            CP_COMMIT();
        }

        // ---- combine maxes, exp in regs, write P ----
        float sc[4], lsum[4];
#pragma unroll
        for (int i = 0; i < 4; i++) {
            int row = rowA0 + (i >> 1) * 16 + (i & 1) * 8;
            float mn = fmaxf(mreg[i], fmaxf(maxbuf[row], maxbuf[ABQ + row]));
            sc[i] = __expf(mreg[i] - mn);
            mreg[i] = mn;
            lsum[i] = 0.0f;
        }
#pragma unroll
        for (int mi = 0; mi < 2; mi++) {
            int rA = rowA0 + mi * 16;
#pragma unroll
            for (int ni = 0; ni < 4; ni++) {
                int col = wn * 32 + ni * 8 + tig * 2;
                uint32_t p0 = f2tf32(__expf(sacc[mi][ni][0] - mreg[mi * 2]));
                uint32_t p1 = f2tf32(__expf(sacc[mi][ni][1] - mreg[mi * 2]));
                uint32_t p2 = f2tf32(__expf(sacc[mi][ni][2] - mreg[mi * 2 + 1]));
                uint32_t p3 = f2tf32(__expf(sacc[mi][ni][3] - mreg[mi * 2 + 1]));
                lsum[mi * 2]     += __uint_as_float(p0) + __uint_as_float(p1);
                lsum[mi * 2 + 1] += __uint_as_float(p2) + __uint_as_float(p3);
                uint2 w0 = { p0, p1 };
                uint2 w1 = { p2, p3 };
                *(uint2*)&Pu[rA * LDPS + col]       = w0;
                *(uint2*)&Pu[(rA + 8) * LDPS + col] = w1;
            }
        }
#pragma unroll
        for (int i = 0; i < 4; i++) {
            float ls = lsum[i];
            ls += __shfl_xor_sync(0xFFFFFFFF, ls, 1);
            ls += __shfl_xor_sync(0xFFFFFFFF, ls, 2);
            lsum[i] = ls;
        }
        if (tig == 0) {
#pragma unroll
            for (int i = 0; i < 4; i++) {
                int row = rowA0 + (i >> 1) * 16 + (i & 1) * 8;
                lbuf[wn * ABQ + row] = lsum[i];
            }
        }

        // V(t) must be resident before PV
        if (t + 1 < NT) { CP_WAIT(1); } else { CP_WAIT(0); }
        __syncthreads();   // P + lbuf visible, Vs(t) visible

#pragma unroll
        for (int i = 0; i < 4; i++) {
            int row = rowA0 + (i >> 1) * 16 + (i & 1) * 8;
            lreg[i] = lreg[i] * sc[i] + lbuf[row] + lbuf[ABQ + row];
        }

        // ---- O rescale + O += P @ V : warp tile 32x64 ----
#pragma unroll
        for (int mi = 0; mi < 2; mi++) {
            float s0 = sc[mi * 2], s1 = sc[mi * 2 + 1];
#pragma unroll
            for (int nj = 0; nj < 8; nj++) {
                o[mi][nj][0] *= s0; o[mi][nj][1] *= s0;
                o[mi][nj][2] *= s1; o[mi][nj][3] *= s1;
            }
        }
#pragma unroll
        for (int ks = 0; ks < 8; ks++) {
            const int kk = ks * 8;
            uint32_t af[2][4], bf[8][2];
#pragma unroll
            for (int mi = 0; mi < 2; mi++) {
                int m = wm * 32 + mi * 16;
                af[mi][0] = Pu[(m + g) * LDPS + kk + tig];
                af[mi][1] = Pu[(m + g + 8) * LDPS + kk + tig];
                af[mi][2] = Pu[(m + g) * LDPS + kk + tig + 4];
                af[mi][3] = Pu[(m + g + 8) * LDPS + kk + tig + 4];
            }
#pragma unroll
            for (int nj = 0; nj < 8; nj++) {
                int n = wn * 64 + nj * 8;
                bf[nj][0] = Vs[(kk + tig) * LDVS + n + g];
                bf[nj][1] = Vs[(kk + tig + 4) * LDVS + n + g];
            }
#pragma unroll
            for (int mi = 0; mi < 2; mi++)
#pragma unroll
                for (int nj = 0; nj < 8; nj++)
                    mma_tf32(o[mi][nj], af[mi], bf[nj]);
        }
        __syncthreads();   // Vs consumed

        // ---- prefetch V(t+1) (overlaps next S-phase) ----
        if (t + 1 < NT) {
            const float* Vn = V + base + (size_t)(t + 1) * ABKV * HIDDEN;
#pragma unroll
            for (int r = 0; r < 8; r++) {
                int kv = ldr + 8 * r;
                cp_async16(vs_u32 + (kv * LDVS + dg) * 4,
                           Vn + (size_t)kv * HIDDEN + dg);
            }
            CP_COMMIT();
        }
    }

    // ---- Epilogue: normalize, round to tf32 (feeds O-proj), store ----
#pragma unroll
    for (int mi = 0; mi < 2; mi++) {
        int r0 = wm * 32 + mi * 16 + g;
        float inv0 = 1.0f / lreg[mi * 2];
        float inv1 = 1.0f / lreg[mi * 2 + 1];
#pragma unroll
        for (int nj = 0; nj < 8; nj++) {
            int col = wn * 64 + nj * 8 + tig * 2;
            float2 a, c;
            a.x = __uint_as_float(f2tf32(o[mi][nj][0] * inv0));
            a.y = __uint_as_float(f2tf32(o[mi][nj][1] * inv0));
            c.x = __uint_as_float(f2tf32(o[mi][nj][2] * inv1));
            c.y = __uint_as_float(f2tf32(o[mi][nj][3] * inv1));
            *(float2*)(O + base + (size_t)(q0 + r0) * HIDDEN + col)     = a;
            *(float2*)(O + base + (size_t)(q0 + r0 + 8) * HIDDEN + col) = c;
        }
    }
}

// ---------------------------------------------------------------------------
// Launch
// ---------------------------------------------------------------------------
extern "C" void kernel_launch(void* const* d_in, const int* in_sizes, int n_in,
                              void* d_out, int out_size)
{
    (void)in_sizes; (void)n_in; (void)out_size;

    const float* hs = (const float*)d_in[0];
    const float* wq = (const float*)d_in[1];
    const float* bq = (const float*)d_in[2];
    const float* wk = (const float*)d_in[3];
    const float* bk = (const float*)d_in[4];
    const float* wv = (const float*)d_in[5];
    const float* bv = (const float*)d_in[6];
    const float* wo = (const float*)d_in[7];
    const float* bo = (const float*)d_in[8];
    float* out = (float*)d_out;

    float *q, *k, *v, *ao, *hsr, *wqr, *wkr, *wvr, *wor, *bqs;
    cudaGetSymbolAddress((void**)&q,   g_q);
    cudaGetSymbolAddress((void**)&k,   g_k);
    cudaGetSymbolAddress((void**)&v,   g_v);
    cudaGetSymbolAddress((void**)&ao,  g_ao);
    cudaGetSymbolAddress((void**)&hsr, g_hs);
    cudaGetSymbolAddress((void**)&wqr, g_wq);
    cudaGetSymbolAddress((void**)&wkr, g_wk);
    cudaGetSymbolAddress((void**)&wvr, g_wv);
    cudaGetSymbolAddress((void**)&wor, g_wo);
    cudaGetSymbolAddress((void**)&bqs, g_bqs);

    cudaFuncSetAttribute(attn_tc_kernel,
                         cudaFuncAttributeMaxDynamicSharedMemorySize,
                         ATTN_SMEM_BYTES);
    cudaFuncSetAttribute(gemm_tf32_kernel,
                         cudaFuncAttributeMaxDynamicSharedMemorySize,
                         GEMM_SMEM_BYTES);

    const float scale = 0.08838834764831845f;  // 1/sqrt(128)

    // ---- prep: round (and pre-scale Q path) once ----
    const int nw4 = HIDDEN * HIDDEN / 4;   // 1,048,576
    const int nh4 = MTOK * HIDDEN / 4;     // 2,097,152
    prep_round_kernel<<<nh4 / 256, 256>>>(hs, hsr, 1.0f, nh4);
    prep_round_kernel<<<nw4 / 256, 256>>>(wq, wqr, scale, nw4);
    prep_round_kernel<<<nw4 / 256, 256>>>(wk, wkr, 1.0f, nw4);
    prep_round_kernel<<<nw4 / 256, 256>>>(wv, wvr, 1.0f, nw4);
    prep_round_kernel<<<nw4 / 256, 256>>>(wo, wor, 1.0f, nw4);
    prep_round_kernel<<<HIDDEN / 4 / 64, 64>>>(bq, bqs, scale, HIDDEN / 4);

    dim3 gemm_grid(HIDDEN / GBN, MTOK / GBM);   // (16, 32)

    // QKV projections (outputs rounded to tf32 for attention)
    gemm_tf32_kernel<<<gemm_grid, 256, GEMM_SMEM_BYTES>>>(hsr, wqr, bqs, q, 1);
    gemm_tf32_kernel<<<gemm_grid, 256, GEMM_SMEM_BYTES>>>(hsr, wkr, bk,  k, 1);
    gemm_tf32_kernel<<<gemm_grid, 256, GEMM_SMEM_BYTES>>>(hsr, wvr, bv,  v, 1);

    dim3 attn_grid(SEQ / ABQ, NHEADS, BATCH);   // (16, 16, 2)
    attn_tc_kernel<<<attn_grid, 256, ATTN_SMEM_BYTES>>>(q, k, v, ao);

    // Output projection (full fp32 output)
    gemm_tf32_kernel<<<gemm_grid, 256, GEMM_SMEM_BYTES>>>(ao, wor, bo, out, 0);
}

// round 13
// speedup vs baseline: 4.8617x; 1.1435x over previous
#include <cuda_runtime.h>
#include <cuda_fp16.h>
#include <math.h>
#include <stdint.h>

// Problem constants (fixed by the reference)
#define HIDDEN 2048
#define NHEADS 16
#define HEADDIM 128
#define BATCH 2
#define SEQ 2048
#define MTOK (BATCH * SEQ)   // 4096

// ---------------------------------------------------------------------------
// Scratch buffers (allocation-free rule: __device__ globals)
// ---------------------------------------------------------------------------
__device__ float  g_q[MTOK * HIDDEN];
__device__ float  g_k[MTOK * HIDDEN];
__device__ float  g_v[MTOK * HIDDEN];
__device__ __half g_ao[MTOK * HIDDEN];       // attention out, fp16 (O-proj input)
__device__ __half g_hs[MTOK * HIDDEN];       // fp16 hidden states
__device__ __half g_wq[HIDDEN * HIDDEN];     // fp16(scale*wq)^T  [N][K]
__device__ __half g_wk[HIDDEN * HIDDEN];     // fp16(wk)^T
__device__ __half g_wv[HIDDEN * HIDDEN];     // fp16(wv)^T
__device__ __half g_wo[HIDDEN * HIDDEN];     // fp16(wo)^T
__device__ float  g_bqs[HIDDEN];             // scale * bq

__device__ __forceinline__ uint32_t f2tf32(float f) {
    uint32_t r;
    asm("cvt.rna.tf32.f32 %0, %1;" : "=r"(r) : "f"(f));
    return r;
}

__device__ __forceinline__ void mma_tf32(float* c, const uint32_t* a, const uint32_t* b) {
    asm volatile(
        "mma.sync.aligned.m16n8k8.row.col.f32.tf32.tf32.f32 "
        "{%0,%1,%2,%3}, {%4,%5,%6,%7}, {%8,%9}, {%0,%1,%2,%3};\n"
        : "+f"(c[0]), "+f"(c[1]), "+f"(c[2]), "+f"(c[3])
        : "r"(a[0]), "r"(a[1]), "r"(a[2]), "r"(a[3]), "r"(b[0]), "r"(b[1]));
}

__device__ __forceinline__ void mma_f16(float* c, const uint32_t* a, const uint32_t* b) {
    asm volatile(
        "mma.sync.aligned.m16n8k16.row.col.f32.f16.f16.f32 "
        "{%0,%1,%2,%3}, {%4,%5,%6,%7}, {%8,%9}, {%0,%1,%2,%3};\n"
        : "+f"(c[0]), "+f"(c[1]), "+f"(c[2]), "+f"(c[3])
        : "r"(a[0]), "r"(a[1]), "r"(a[2]), "r"(a[3]), "r"(b[0]), "r"(b[1]));
}

__device__ __forceinline__ void cp_async16(uint32_t smem_addr, const void* gptr) {
    asm volatile("cp.async.cg.shared.global [%0], [%1], 16;"
                 :: "r"(smem_addr), "l"(gptr));
}
#define CP_COMMIT() asm volatile("cp.async.commit_group;" ::: "memory")
#define CP_WAIT(N)  asm volatile("cp.async.wait_group %0;" :: "n"(N) : "memory")

__device__ __forceinline__ uint32_t smem_u32(const void* p) {
    return (uint32_t)__cvta_generic_to_shared(p);
}

// ---------------------------------------------------------------------------
// Prep kernels
// ---------------------------------------------------------------------------
__global__ void prep_round_half(const float* __restrict__ src,
                                __half* __restrict__ dst,
                                float mul, int n4)
{
    int i = blockIdx.x * blockDim.x + threadIdx.x;
    if (i < n4) {
        float4 v = *(const float4*)(src + i * 4);
        __half2 h0 = __floats2half2_rn(v.x * mul, v.y * mul);
        __half2 h1 = __floats2half2_rn(v.z * mul, v.w * mul);
        *(__half2*)(dst + i * 4)     = h0;
        *(__half2*)(dst + i * 4 + 2) = h1;
    }
}

__global__ void prep_round_kernel(const float* __restrict__ src,
                                  float* __restrict__ dst,
                                  float mul, int n4)
{
    int i = blockIdx.x * blockDim.x + threadIdx.x;
    if (i < n4) {
        float4 v = *(const float4*)(src + i * 4);
        float4 o;
        o.x = v.x * mul; o.y = v.y * mul; o.z = v.z * mul; o.w = v.w * mul;
        *(float4*)(dst + i * 4) = o;
    }
}

// W[K][N] -> Wt[N][K] fp16 (with optional scale)
__global__ void prep_transpose_half(const float* __restrict__ src,
                                    __half* __restrict__ dst, float mul)
{
    __shared__ float t[32][33];
    int bx = blockIdx.x * 32, by = blockIdx.y * 32;
    int tx = threadIdx.x, ty = threadIdx.y;
#pragma unroll
    for (int j = 0; j < 4; j++)
        t[ty + 8 * j][tx] = src[(size_t)(by + ty + 8 * j) * HIDDEN + bx + tx];
    __syncthreads();
#pragma unroll
    for (int j = 0; j < 4; j++)
        dst[(size_t)(bx + ty + 8 * j) * HIDDEN + by + tx] =
            __float2half_rn(t[tx][ty + 8 * j] * mul);
}

// ---------------------------------------------------------------------------
// FP16 tensor-core GEMM: C[M,N](f32) = A[M,K](f16) @ Wt[N,K](f16)^T + bias
// 128x128x64 tile, 256 threads, 2 CTAs/SM, 2-stage cp.async pipeline.
// ---------------------------------------------------------------------------
#define GBM 128
#define GBN 128
#define GBK 64
#define GRS 36    // row stride in u32 words (64 halves = 32 words + 4 pad)
#define G_STG_WORDS (GBM * GRS)                    // 4608 words per operand stage
#define GEMM_SMEM_WORDS (4 * G_STG_WORDS)          // A0,A1,B0,B1
#define GEMM_SMEM_BYTES (GEMM_SMEM_WORDS * 4)      // 73728

__global__ __launch_bounds__(256, 2)
void gemm_f16_kernel(const __half* __restrict__ A,
                     const __half* __restrict__ Wt,
                     const float* __restrict__ bias,
                     float* __restrict__ C,
                     int round_out)
{
    extern __shared__ uint32_t gsm[];
    uint32_t* Asm = gsm;                       // [2][GBM][GRS]
    uint32_t* Bsm = gsm + 2 * G_STG_WORDS;     // [2][GBN][GRS]
    const uint32_t as_u32 = smem_u32(Asm);
    const uint32_t bs_u32 = smem_u32(Bsm);

    const int tid  = threadIdx.x;
    const int lane = tid & 31;
    const int warp = tid >> 5;
    const int wm   = warp >> 2;      // 0..1 -> rows wm*64
    const int wn   = warp & 3;       // 0..3 -> cols wn*32
    const int g    = lane >> 2;
    const int tig  = lane & 3;

    const int bm = blockIdx.y * GBM;
    const int bn = blockIdx.x * GBN;

    // async fill: 1024 16B chunks per operand / 256 thr = 4 each
    const int f_row = tid >> 1;            // 0..127
    const int f_ch0 = (tid & 1) * 4;       // 0 or 4 (chunks 0-3 / 4-7 split)

    auto fill = [&](int kt) {
        const int s = kt & 1;
        const __half* Ag = A  + (size_t)bm * HIDDEN + kt * GBK;
        const __half* Bg = Wt + (size_t)bn * HIDDEN + kt * GBK;
        const uint32_t abase = as_u32 + s * G_STG_WORDS * 4;
        const uint32_t bbase = bs_u32 + s * G_STG_WORDS * 4;
#pragma unroll
        for (int c = 0; c < 4; c++) {
            int ch = f_ch0 + c;
            cp_async16(abase + f_row * (GRS * 4) + ch * 16,
                       Ag + (size_t)f_row * HIDDEN + ch * 8);
            cp_async16(bbase + f_row * (GRS * 4) + ch * 16,
                       Bg + (size_t)f_row * HIDDEN + ch * 8);
        }
        CP_COMMIT();
    };

    float acc[4][4][4];
#pragma unroll
    for (int mi = 0; mi < 4; mi++)
#pragma unroll
        for (int ni = 0; ni < 4; ni++)
#pragma unroll
            for (int r = 0; r < 4; r++) acc[mi][ni][r] = 0.0f;

    const int nk = HIDDEN / GBK;   // 32
    fill(0);

    for (int kt = 0; kt < nk; kt++) {
        if (kt + 1 < nk) { fill(kt + 1); CP_WAIT(1); }
        else             { CP_WAIT(0); }
        __syncthreads();

        const uint32_t* As = Asm + (kt & 1) * G_STG_WORDS;
        const uint32_t* Bs = Bsm + (kt & 1) * G_STG_WORDS;
#pragma unroll
        for (int ks = 0; ks < 4; ks++) {
            const int kk2 = ks * 8;   // u32 offset (16 halves per step)
            uint32_t af[4][4], bf[4][2];
#pragma unroll
            for (int mi = 0; mi < 4; mi++) {
                int m = wm * 64 + mi * 16;
                af[mi][0] = As[(m + g) * GRS + kk2 + tig];
                af[mi][1] = As[(m + g + 8) * GRS + kk2 + tig];
                af[mi][2] = As[(m + g) * GRS + kk2 + tig + 4];
                af[mi][3] = As[(m + g + 8) * GRS + kk2 + tig + 4];
            }
#pragma unroll
            for (int ni = 0; ni < 4; ni++) {
                int n = wn * 32 + ni * 8;
                bf[ni][0] = Bs[(n + g) * GRS + kk2 + tig];
                bf[ni][1] = Bs[(n + g) * GRS + kk2 + tig + 4];
            }
#pragma unroll
            for (int mi = 0; mi < 4; mi++)
#pragma unroll
                for (int ni = 0; ni < 4; ni++)
                    mma_f16(acc[mi][ni], af[mi], bf[ni]);
        }
        __syncthreads();
    }

    // ---- epilogue: bias + store ----
#pragma unroll
    for (int ni = 0; ni < 4; ni++) {
        int col = bn + wn * 32 + ni * 8 + tig * 2;
        float b0 = bias[col], b1 = bias[col + 1];
#pragma unroll
        for (int mi = 0; mi < 4; mi++) {
            int row = bm + wm * 64 + mi * 16 + g;
            float v00 = acc[mi][ni][0] + b0, v01 = acc[mi][ni][1] + b1;
            float v10 = acc[mi][ni][2] + b0, v11 = acc[mi][ni][3] + b1;
            if (round_out) {
                v00 = __uint_as_float(f2tf32(v00));
                v01 = __uint_as_float(f2tf32(v01));
                v10 = __uint_as_float(f2tf32(v10));
                v11 = __uint_as_float(f2tf32(v11));
            }
            float2 r0 = { v00, v01 };
            float2 r1 = { v10, v11 };
            *(float2*)(C + (size_t)row * HIDDEN + col)       = r0;
            *(float2*)(C + (size_t)(row + 8) * HIDDEN + col) = r1;
        }
    }
}

// ---------------------------------------------------------------------------
// Tensor-core flash attention (tf32, round-8 proven) — epilogue emits fp16.
// ---------------------------------------------------------------------------
#define ABQ 128
#define ABKV 64
#define LDQS 132
#define LDKS 132
#define LDVS 136
#define LDPS 66

#define AS_QS 0
#define AS_KS (AS_QS + ABQ * LDQS)
#define AS_VS (AS_KS + ABKV * LDKS)
#define AS_PS (AS_VS + ABKV * LDVS)
#define AS_MB (AS_PS + ABQ * LDPS)
#define AS_LB (AS_MB + 2 * ABQ)
#define AS_TOT (AS_LB + 2 * ABQ)
#define ATTN_SMEM_BYTES (AS_TOT * 4)

__global__ __launch_bounds__(256)
void attn_tc_kernel(const float* __restrict__ Q,
                    const float* __restrict__ K,
                    const float* __restrict__ V,
                    __half* __restrict__ O)
{
    extern __shared__ float sm[];
    uint32_t* Qs = (uint32_t*)(sm + AS_QS);
    uint32_t* Ks = (uint32_t*)(sm + AS_KS);
    uint32_t* Vs = (uint32_t*)(sm + AS_VS);
    uint32_t* Pu = (uint32_t*)(sm + AS_PS);
    float* maxbuf = sm + AS_MB;
    float* lbuf   = sm + AS_LB;
    const uint32_t qs_u32 = smem_u32(Qs);
    const uint32_t ks_u32 = smem_u32(Ks);
    const uint32_t vs_u32 = smem_u32(Vs);

    const int tid  = threadIdx.x;
    const int lane = tid & 31;
    const int warp = tid >> 5;
    const int g    = lane >> 2;
    const int tig  = lane & 3;
    const int wm   = warp >> 1;
    const int wn   = warp & 1;

    const int q0 = blockIdx.x * ABQ;
    const int h  = blockIdx.y;
    const int b  = blockIdx.z;
    const size_t base = (size_t)b * SEQ * HIDDEN + (size_t)h * HEADDIM;

    const int rowA0 = wm * 32 + g;
    float mreg[4] = { -INFINITY, -INFINITY, -INFINITY, -INFINITY };
    float lreg[4] = { 0.0f, 0.0f, 0.0f, 0.0f };

    const int ldr = tid >> 5;
    const int dg  = lane * 4;

#pragma unroll
    for (int r = 0; r < 16; r++) {
        int q = ldr + 8 * r;
        cp_async16(qs_u32 + (q * LDQS + dg) * 4,
                   Q + base + (size_t)(q0 + q) * HIDDEN + dg);
    }
    CP_COMMIT();
#pragma unroll
    for (int r = 0; r < 8; r++) {
        int kv = ldr + 8 * r;
        cp_async16(ks_u32 + (kv * LDKS + dg) * 4,
                   K + base + (size_t)kv * HIDDEN + dg);
    }
    CP_COMMIT();
#pragma unroll
    for (int r = 0; r < 8; r++) {
        int kv = ldr + 8 * r;
        cp_async16(vs_u32 + (kv * LDVS + dg) * 4,
                   V + base + (size_t)kv * HIDDEN + dg);
    }
    CP_COMMIT();

    float o[2][8][4];
#pragma unroll
    for (int mi = 0; mi < 2; mi++)
#pragma unroll
        for (int nj = 0; nj < 8; nj++)
#pragma unroll
            for (int r = 0; r < 4; r++) o[mi][nj][r] = 0.0f;

    const int NT = SEQ / ABKV;
    for (int t = 0; t < NT; t++) {
        CP_WAIT(1);
        __syncthreads();

        float sacc[2][4][4];
#pragma unroll
        for (int mi = 0; mi < 2; mi++)
#pragma unroll
            for (int ni = 0; ni < 4; ni++)
#pragma unroll
                for (int r = 0; r < 4; r++) sacc[mi][ni][r] = 0.0f;

#pragma unroll
        for (int ks = 0; ks < 16; ks++) {
            const int kk = ks * 8;
            uint32_t af[2][4], bf[4][2];
#pragma unroll
            for (int mi = 0; mi < 2; mi++) {
                int m = wm * 32 + mi * 16;
                af[mi][0] = Qs[(m + g) * LDQS + kk + tig];
                af[mi][1] = Qs[(m + g + 8) * LDQS + kk + tig];
                af[mi][2] = Qs[(m + g) * LDQS + kk + tig + 4];
                af[mi][3] = Qs[(m + g + 8) * LDQS + kk + tig + 4];
            }
#pragma unroll
            for (int ni = 0; ni < 4; ni++) {
                int n = wn * 32 + ni * 8;
                bf[ni][0] = Ks[(n + g) * LDKS + kk + tig];
                bf[ni][1] = Ks[(n + g) * LDKS + kk + tig + 4];
            }
#pragma unroll
            for (int mi = 0; mi < 2; mi++)
#pragma unroll
                for (int ni = 0; ni < 4; ni++)
                    mma_tf32(sacc[mi][ni], af[mi], bf[ni]);
        }

#pragma unroll
        for (int mi = 0; mi < 2; mi++) {
            float a = -INFINITY, c = -INFINITY;
#pragma unroll
            for (int ni = 0; ni < 4; ni++) {
                a = fmaxf(a, fmaxf(sacc[mi][ni][0], sacc[mi][ni][1]));
                c = fmaxf(c, fmaxf(sacc[mi][ni][2], sacc[mi][ni][3]));
            }
            a = fmaxf(a, __shfl_xor_sync(0xFFFFFFFF, a, 1));
            a = fmaxf(a, __shfl_xor_sync(0xFFFFFFFF, a, 2));
            c = fmaxf(c, __shfl_xor_sync(0xFFFFFFFF, c, 1));
            c = fmaxf(c, __shfl_xor_sync(0xFFFFFFFF, c, 2));
            if (tig == 0) {
                maxbuf[wn * ABQ + rowA0 + mi * 16]     = a;
                maxbuf[wn * ABQ + rowA0 + mi * 16 + 8] = c;
            }
        }
        __syncthreads();

        if (t + 1 < NT) {
            const float* Kn = K + base + (size_t)(t + 1) * ABKV * HIDDEN;
#pragma unroll
            for (int r = 0; r < 8; r++) {
                int kv = ldr + 8 * r;
                cp_async16(ks_u32 + (kv * LDKS + dg) * 4,
                           Kn + (size_t)kv * HIDDEN + dg);
            }
            CP_COMMIT();
        }

        float sc[4], lsum[4];
#pragma unroll
        for (int i = 0; i < 4; i++) {
            int row = rowA0 + (i >> 1) * 16 + (i & 1) * 8;
            float mn = fmaxf(mreg[i], fmaxf(maxbuf[row], maxbuf[ABQ + row]));
            sc[i] = __expf(mreg[i] - mn);
            mreg[i] = mn;
            lsum[i] = 0.0f;
        }
#pragma unroll
        for (int mi = 0; mi < 2; mi++) {
            int rA = rowA0 + mi * 16;
#pragma unroll
            for (int ni = 0; ni < 4; ni++) {
                int col = wn * 32 + ni * 8 + tig * 2;
                uint32_t p0 = f2tf32(__expf(sacc[mi][ni][0] - mreg[mi * 2]));
                uint32_t p1 = f2tf32(__expf(sacc[mi][ni][1] - mreg[mi * 2]));
                uint32_t p2 = f2tf32(__expf(sacc[mi][ni][2] - mreg[mi * 2 + 1]));
                uint32_t p3 = f2tf32(__expf(sacc[mi][ni][3] - mreg[mi * 2 + 1]));
                lsum[mi * 2]     += __uint_as_float(p0) + __uint_as_float(p1);
                lsum[mi * 2 + 1] += __uint_as_float(p2) + __uint_as_float(p3);
                uint2 w0 = { p0, p1 };
                uint2 w1 = { p2, p3 };
                *(uint2*)&Pu[rA * LDPS + col]       = w0;
                *(uint2*)&Pu[(rA + 8) * LDPS + col] = w1;
            }
        }
#pragma unroll
        for (int i = 0; i < 4; i++) {
            float ls = lsum[i];
            ls += __shfl_xor_sync(0xFFFFFFFF, ls, 1);
            ls += __shfl_xor_sync(0xFFFFFFFF, ls, 2);
            lsum[i] = ls;
        }
        if (tig == 0) {
#pragma unroll
            for (int i = 0; i < 4; i++) {
                int row = rowA0 + (i >> 1) * 16 + (i & 1) * 8;
                lbuf[wn * ABQ + row] = lsum[i];
            }
        }

        if (t + 1 < NT) { CP_WAIT(1); } else { CP_WAIT(0); }
        __syncthreads();

#pragma unroll
        for (int i = 0; i < 4; i++) {
            int row = rowA0 + (i >> 1) * 16 + (i & 1) * 8;
            lreg[i] = lreg[i] * sc[i] + lbuf[row] + lbuf[ABQ + row];
        }

#pragma unroll
        for (int mi = 0; mi < 2; mi++) {
            float s0 = sc[mi * 2], s1 = sc[mi * 2 + 1];
#pragma unroll
            for (int nj = 0; nj < 8; nj++) {
                o[mi][nj][0] *= s0; o[mi][nj][1] *= s0;
                o[mi][nj][2] *= s1; o[mi][nj][3] *= s1;
            }
        }
#pragma unroll
        for (int ks = 0; ks < 8; ks++) {
            const int kk = ks * 8;
            uint32_t af[2][4], bf[8][2];
#pragma unroll
            for (int mi = 0; mi < 2; mi++) {
                int m = wm * 32 + mi * 16;
                af[mi][0] = Pu[(m + g) * LDPS + kk + tig];
                af[mi][1] = Pu[(m + g + 8) * LDPS + kk + tig];
                af[mi][2] = Pu[(m + g) * LDPS + kk + tig + 4];
                af[mi][3] = Pu[(m + g + 8) * LDPS + kk + tig + 4];
            }
#pragma unroll
            for (int nj = 0; nj < 8; nj++) {
                int n = wn * 64 + nj * 8;
                bf[nj][0] = Vs[(kk + tig) * LDVS + n + g];
                bf[nj][1] = Vs[(kk + tig + 4) * LDVS + n + g];
            }
#pragma unroll
            for (int mi = 0; mi < 2; mi++)
#pragma unroll
                for (int nj = 0; nj < 8; nj++)
                    mma_tf32(o[mi][nj], af[mi], bf[nj]);
        }
        __syncthreads();

        if (t + 1 < NT) {
            const float* Vn = V + base + (size_t)(t + 1) * ABKV * HIDDEN;
#pragma unroll
            for (int r = 0; r < 8; r++) {
                int kv = ldr + 8 * r;
                cp_async16(vs_u32 + (kv * LDVS + dg) * 4,
                           Vn + (size_t)kv * HIDDEN + dg);
            }
            CP_COMMIT();
        }
    }

    // ---- Epilogue: normalize, convert fp16 (feeds O-proj), store ----
#pragma unroll
    for (int mi = 0; mi < 2; mi++) {
        int r0 = wm * 32 + mi * 16 + g;
        float inv0 = 1.0f / lreg[mi * 2];
        float inv1 = 1.0f / lreg[mi * 2 + 1];
#pragma unroll
        for (int nj = 0; nj < 8; nj++) {
            int col = wn * 64 + nj * 8 + tig * 2;
            __half2 a = __floats2half2_rn(o[mi][nj][0] * inv0, o[mi][nj][1] * inv0);
            __half2 c = __floats2half2_rn(o[mi][nj][2] * inv1, o[mi][nj][3] * inv1);
            *(__half2*)(O + base + (size_t)(q0 + r0) * HIDDEN + col)     = a;
            *(__half2*)(O + base + (size_t)(q0 + r0 + 8) * HIDDEN + col) = c;
        }
    }
}

// ---------------------------------------------------------------------------
// Launch
// ---------------------------------------------------------------------------
extern "C" void kernel_launch(void* const* d_in, const int* in_sizes, int n_in,
                              void* d_out, int out_size)
{
    (void)in_sizes; (void)n_in; (void)out_size;

    const float* hs = (const float*)d_in[0];
    const float* wq = (const float*)d_in[1];
    const float* bq = (const float*)d_in[2];
    const float* wk = (const float*)d_in[3];
    const float* bk = (const float*)d_in[4];
    const float* wv = (const float*)d_in[5];
    const float* bv = (const float*)d_in[6];
    const float* wo = (const float*)d_in[7];
    const float* bo = (const float*)d_in[8];
    float* out = (float*)d_out;

    float *q, *k, *v, *bqs;
    __half *ao, *hsr, *wqr, *wkr, *wvr, *wor;
    cudaGetSymbolAddress((void**)&q,   g_q);
    cudaGetSymbolAddress((void**)&k,   g_k);
    cudaGetSymbolAddress((void**)&v,   g_v);
    cudaGetSymbolAddress((void**)&ao,  g_ao);
    cudaGetSymbolAddress((void**)&hsr, g_hs);
    cudaGetSymbolAddress((void**)&wqr, g_wq);
    cudaGetSymbolAddress((void**)&wkr, g_wk);
    cudaGetSymbolAddress((void**)&wvr, g_wv);
    cudaGetSymbolAddress((void**)&wor, g_wo);
    cudaGetSymbolAddress((void**)&bqs, g_bqs);

    cudaFuncSetAttribute(attn_tc_kernel,
                         cudaFuncAttributeMaxDynamicSharedMemorySize,
                         ATTN_SMEM_BYTES);
    cudaFuncSetAttribute(gemm_f16_kernel,
                         cudaFuncAttributeMaxDynamicSharedMemorySize,
                         GEMM_SMEM_BYTES);

    const float scale = 0.08838834764831845f;  // 1/sqrt(128)

    // ---- prep: fp16 conversions ----
    const int nh4 = MTOK * HIDDEN / 4;
    prep_round_half<<<nh4 / 256, 256>>>(hs, hsr, 1.0f, nh4);
    dim3 tgrid(HIDDEN / 32, HIDDEN / 32), tblk(32, 8);
    prep_transpose_half<<<tgrid, tblk>>>(wq, wqr, scale);
    prep_transpose_half<<<tgrid, tblk>>>(wk, wkr, 1.0f);
    prep_transpose_half<<<tgrid, tblk>>>(wv, wvr, 1.0f);
    prep_transpose_half<<<tgrid, tblk>>>(wo, wor, 1.0f);
    prep_round_kernel<<<HIDDEN / 4 / 64, 64>>>(bq, bqs, scale, HIDDEN / 4);

    dim3 gemm_grid(HIDDEN / GBN, MTOK / GBM);   // (16, 32)

    // QKV projections (fp16 mma; outputs tf32-rounded fp32 for attention)
    gemm_f16_kernel<<<gemm_grid, 256, GEMM_SMEM_BYTES>>>(hsr, wqr, bqs, q, 1);
    gemm_f16_kernel<<<gemm_grid, 256, GEMM_SMEM_BYTES>>>(hsr, wkr, bk,  k, 1);
    gemm_f16_kernel<<<gemm_grid, 256, GEMM_SMEM_BYTES>>>(hsr, wvr, bv,  v, 1);

    dim3 attn_grid(SEQ / ABQ, NHEADS, BATCH);   // (16, 16, 2)
    attn_tc_kernel<<<attn_grid, 256, ATTN_SMEM_BYTES>>>(q, k, v, ao);

    // Output projection (fp16 mma, fp32 out)
    gemm_f16_kernel<<<gemm_grid, 256, GEMM_SMEM_BYTES>>>(ao, wor, bo, out, 0);
}

// round 14
// speedup vs baseline: 5.6320x; 1.1585x over previous
#include <cuda_runtime.h>
#include <cuda_fp16.h>
#include <math.h>
#include <stdint.h>

// Problem constants (fixed by the reference)
#define HIDDEN 2048
#define NHEADS 16
#define HEADDIM 128
#define BATCH 2
#define SEQ 2048
#define MTOK (BATCH * SEQ)   // 4096

// ---------------------------------------------------------------------------
// Scratch buffers (allocation-free rule: __device__ globals)
// ---------------------------------------------------------------------------
__device__ __half g_q[MTOK * HIDDEN];        // fp16 Q (pre-scaled)
__device__ __half g_k[MTOK * HIDDEN];        // fp16 K
__device__ __half g_v[MTOK * HIDDEN];        // fp16 V
__device__ __half g_ao[MTOK * HIDDEN];       // attention out fp16
__device__ __half g_hs[MTOK * HIDDEN];       // fp16 hidden states
__device__ __half g_wq[HIDDEN * HIDDEN];     // fp16(scale*wq)^T  [N][K]
__device__ __half g_wk[HIDDEN * HIDDEN];
__device__ __half g_wv[HIDDEN * HIDDEN];
__device__ __half g_wo[HIDDEN * HIDDEN];
__device__ float  g_bqs[HIDDEN];             // scale * bq

__device__ __forceinline__ void mma_f16(float* c, const uint32_t* a, const uint32_t* b) {
    asm volatile(
        "mma.sync.aligned.m16n8k16.row.col.f32.f16.f16.f32 "
        "{%0,%1,%2,%3}, {%4,%5,%6,%7}, {%8,%9}, {%0,%1,%2,%3};\n"
        : "+f"(c[0]), "+f"(c[1]), "+f"(c[2]), "+f"(c[3])
        : "r"(a[0]), "r"(a[1]), "r"(a[2]), "r"(a[3]), "r"(b[0]), "r"(b[1]));
}

__device__ __forceinline__ void ldsm_x2_trans(uint32_t& r0, uint32_t& r1, uint32_t addr) {
    asm volatile("ldmatrix.sync.aligned.m8n8.x2.trans.shared.b16 {%0,%1}, [%2];"
                 : "=r"(r0), "=r"(r1) : "r"(addr));
}

__device__ __forceinline__ void cp_async16(uint32_t smem_addr, const void* gptr) {
    asm volatile("cp.async.cg.shared.global [%0], [%1], 16;"
                 :: "r"(smem_addr), "l"(gptr));
}
#define CP_COMMIT() asm volatile("cp.async.commit_group;" ::: "memory")
#define CP_WAIT(N)  asm volatile("cp.async.wait_group %0;" :: "n"(N) : "memory")

__device__ __forceinline__ uint32_t smem_u32(const void* p) {
    return (uint32_t)__cvta_generic_to_shared(p);
}

// ---------------------------------------------------------------------------
// Prep kernels
// ---------------------------------------------------------------------------
__global__ void prep_round_half(const float* __restrict__ src,
                                __half* __restrict__ dst,
                                float mul, int n4)
{
    int i = blockIdx.x * blockDim.x + threadIdx.x;
    if (i < n4) {
        float4 v = *(const float4*)(src + i * 4);
        *(__half2*)(dst + i * 4)     = __floats2half2_rn(v.x * mul, v.y * mul);
        *(__half2*)(dst + i * 4 + 2) = __floats2half2_rn(v.z * mul, v.w * mul);
    }
}

__global__ void prep_scale_kernel(const float* __restrict__ src,
                                  float* __restrict__ dst,
                                  float mul, int n4)
{
    int i = blockIdx.x * blockDim.x + threadIdx.x;
    if (i < n4) {
        float4 v = *(const float4*)(src + i * 4);
        float4 o = { v.x * mul, v.y * mul, v.z * mul, v.w * mul };
        *(float4*)(dst + i * 4) = o;
    }
}

// W[K][N] -> Wt[N][K] fp16 (with optional scale)
__global__ void prep_transpose_half(const float* __restrict__ src,
                                    __half* __restrict__ dst, float mul)
{
    __shared__ float t[32][33];
    int bx = blockIdx.x * 32, by = blockIdx.y * 32;
    int tx = threadIdx.x, ty = threadIdx.y;
#pragma unroll
    for (int j = 0; j < 4; j++)
        t[ty + 8 * j][tx] = src[(size_t)(by + ty + 8 * j) * HIDDEN + bx + tx];
    __syncthreads();
#pragma unroll
    for (int j = 0; j < 4; j++)
        dst[(size_t)(bx + ty + 8 * j) * HIDDEN + by + tx] =
            __float2half_rn(t[tx][ty + 8 * j] * mul);
}

// ---------------------------------------------------------------------------
// FP16 tensor-core GEMM: C = A[M,K](f16) @ Wt[N,K](f16)^T + bias
// Output fp16 (Ch) or fp32 (Cf). 128x128x64 tile, 256 thr, 2 CTA/SM, 2-stage.
// ---------------------------------------------------------------------------
#define GBM 128
#define GBN 128
#define GBK 64
#define GRS 36    // row stride in u32 words (64 halves = 32 words + 4 pad)
#define G_STG_WORDS (GBM * GRS)
#define GEMM_SMEM_BYTES (4 * G_STG_WORDS * 4)   // 73728

__global__ __launch_bounds__(256, 2)
void gemm_f16_kernel(const __half* __restrict__ A,
                     const __half* __restrict__ Wt,
                     const float* __restrict__ bias,
                     float* __restrict__ Cf,
                     __half* __restrict__ Ch)
{
    extern __shared__ uint32_t gsm[];
    uint32_t* Asm = gsm;
    uint32_t* Bsm = gsm + 2 * G_STG_WORDS;
    const uint32_t as_u32 = smem_u32(Asm);
    const uint32_t bs_u32 = smem_u32(Bsm);

    const int tid  = threadIdx.x;
    const int lane = tid & 31;
    const int warp = tid >> 5;
    const int wm   = warp >> 2;
    const int wn   = warp & 3;
    const int g    = lane >> 2;
    const int tig  = lane & 3;

    const int bm = blockIdx.y * GBM;
    const int bn = blockIdx.x * GBN;

    const int f_row = tid >> 1;
    const int f_ch0 = (tid & 1) * 4;

    auto fill = [&](int kt) {
        const int s = kt & 1;
        const __half* Ag = A  + (size_t)bm * HIDDEN + kt * GBK;
        const __half* Bg = Wt + (size_t)bn * HIDDEN + kt * GBK;
        const uint32_t abase = as_u32 + s * G_STG_WORDS * 4;
        const uint32_t bbase = bs_u32 + s * G_STG_WORDS * 4;
#pragma unroll
        for (int c = 0; c < 4; c++) {
            int ch = f_ch0 + c;
            cp_async16(abase + f_row * (GRS * 4) + ch * 16,
                       Ag + (size_t)f_row * HIDDEN + ch * 8);
            cp_async16(bbase + f_row * (GRS * 4) + ch * 16,
                       Bg + (size_t)f_row * HIDDEN + ch * 8);
        }
        CP_COMMIT();
    };

    float acc[4][4][4];
#pragma unroll
    for (int mi = 0; mi < 4; mi++)
#pragma unroll
        for (int ni = 0; ni < 4; ni++)
#pragma unroll
            for (int r = 0; r < 4; r++) acc[mi][ni][r] = 0.0f;

    const int nk = HIDDEN / GBK;   // 32
    fill(0);

    for (int kt = 0; kt < nk; kt++) {
        if (kt + 1 < nk) { fill(kt + 1); CP_WAIT(1); }
        else             { CP_WAIT(0); }
        __syncthreads();

        const uint32_t* As = Asm + (kt & 1) * G_STG_WORDS;
        const uint32_t* Bs = Bsm + (kt & 1) * G_STG_WORDS;
#pragma unroll
        for (int ks = 0; ks < 4; ks++) {
            const int kk2 = ks * 8;
            uint32_t af[4][4], bf[4][2];
#pragma unroll
            for (int mi = 0; mi < 4; mi++) {
                int m = wm * 64 + mi * 16;
                af[mi][0] = As[(m + g) * GRS + kk2 + tig];
                af[mi][1] = As[(m + g + 8) * GRS + kk2 + tig];
                af[mi][2] = As[(m + g) * GRS + kk2 + tig + 4];
                af[mi][3] = As[(m + g + 8) * GRS + kk2 + tig + 4];
            }
#pragma unroll
            for (int ni = 0; ni < 4; ni++) {
                int n = wn * 32 + ni * 8;
                bf[ni][0] = Bs[(n + g) * GRS + kk2 + tig];
                bf[ni][1] = Bs[(n + g) * GRS + kk2 + tig + 4];
            }
#pragma unroll
            for (int mi = 0; mi < 4; mi++)
#pragma unroll
                for (int ni = 0; ni < 4; ni++)
                    mma_f16(acc[mi][ni], af[mi], bf[ni]);
        }
        __syncthreads();
    }

    // ---- epilogue ----
#pragma unroll
    for (int ni = 0; ni < 4; ni++) {
        int col = bn + wn * 32 + ni * 8 + tig * 2;
        float b0 = bias[col], b1 = bias[col + 1];
#pragma unroll
        for (int mi = 0; mi < 4; mi++) {
            int row = bm + wm * 64 + mi * 16 + g;
            float v00 = acc[mi][ni][0] + b0, v01 = acc[mi][ni][1] + b1;
            float v10 = acc[mi][ni][2] + b0, v11 = acc[mi][ni][3] + b1;
            if (Ch) {
                *(__half2*)(Ch + (size_t)row * HIDDEN + col)       = __floats2half2_rn(v00, v01);
                *(__half2*)(Ch + (size_t)(row + 8) * HIDDEN + col) = __floats2half2_rn(v10, v11);
            } else {
                float2 r0 = { v00, v01 };
                float2 r1 = { v10, v11 };
                *(float2*)(Cf + (size_t)row * HIDDEN + col)       = r0;
                *(float2*)(Cf + (size_t)(row + 8) * HIDDEN + col) = r1;
            }
        }
    }
}

// ---------------------------------------------------------------------------
// FP16 tensor-core flash attention, 256 threads, BQ=128, BKV=64.
// S and PV via m16n8k16.f16; V fragments via ldmatrix.x2.trans.
// ---------------------------------------------------------------------------
#define ABQ 128
#define ABKV 64
#define LQK 68    // Q/K row stride, u32 words (128 halves = 64 words + 4 pad)
#define LVW 68    // V row stride (272 B -> ldmatrix rows on banks 4r)
#define LPW 36    // P row stride (64 halves = 32 words + 4 pad)

#define AS_QS 0
#define AS_KS (AS_QS + ABQ * LQK)         // 8704
#define AS_VS (AS_KS + ABKV * LQK)        // 13056
#define AS_PS (AS_VS + ABKV * LVW)        // 17408
#define AS_MB (AS_PS + ABQ * LPW)         // 22016
#define AS_LB (AS_MB + 2 * ABQ)           // 22272
#define AS_TOT (AS_LB + 2 * ABQ)          // 22528 words
#define ATTN_SMEM_BYTES (AS_TOT * 4)      // 90112 B

__global__ __launch_bounds__(256)
void attn_f16_kernel(const __half* __restrict__ Q,
                     const __half* __restrict__ K,
                     const __half* __restrict__ V,
                     __half* __restrict__ O)
{
    extern __shared__ float sm[];
    uint32_t* Qs = (uint32_t*)(sm + AS_QS);
    uint32_t* Ks = (uint32_t*)(sm + AS_KS);
    uint32_t* Pu = (uint32_t*)(sm + AS_PS);
    float* maxbuf = sm + AS_MB;
    float* lbuf   = sm + AS_LB;
    const uint32_t qs_u32 = smem_u32(sm + AS_QS);
    const uint32_t ks_u32 = smem_u32(sm + AS_KS);
    const uint32_t vs_u32 = smem_u32(sm + AS_VS);

    const int tid  = threadIdx.x;
    const int lane = tid & 31;
    const int warp = tid >> 5;
    const int g    = lane >> 2;
    const int tig  = lane & 3;
    const int wm   = warp >> 1;    // 0..3 -> q rows wm*32
    const int wn   = warp & 1;     // 0..1 -> kv slab (S) / d slab (PV)

    const int q0 = blockIdx.x * ABQ;
    const int h  = blockIdx.y;
    const int b  = blockIdx.z;
    const size_t base = (size_t)b * SEQ * HIDDEN + (size_t)h * HEADDIM;

    const int rowA0 = wm * 32 + g;
    float mreg[4] = { -INFINITY, -INFINITY, -INFINITY, -INFINITY };
    float lreg[4] = { 0.0f, 0.0f, 0.0f, 0.0f };

    // load index helpers: Q 2048 chunks (8/thr), K/V 1024 chunks (4/thr)
    const int qrow = tid >> 1, qch0 = (tid & 1) * 8;
    const int krow = tid >> 2, kch0 = (tid & 3) * 4;

    // ---- prologue: Q, K(0), V(0) ----
#pragma unroll
    for (int c = 0; c < 8; c++)
        cp_async16(qs_u32 + qrow * (LQK * 4) + (qch0 + c) * 16,
                   Q + base + (size_t)(q0 + qrow) * HIDDEN + (qch0 + c) * 8);
    CP_COMMIT();
#pragma unroll
    for (int c = 0; c < 4; c++)
        cp_async16(ks_u32 + krow * (LQK * 4) + (kch0 + c) * 16,
                   K + base + (size_t)krow * HIDDEN + (kch0 + c) * 8);
    CP_COMMIT();
#pragma unroll
    for (int c = 0; c < 4; c++)
        cp_async16(vs_u32 + krow * (LVW * 4) + (kch0 + c) * 16,
                   V + base + (size_t)krow * HIDDEN + (kch0 + c) * 8);
    CP_COMMIT();

    float o[2][8][4];
#pragma unroll
    for (int mi = 0; mi < 2; mi++)
#pragma unroll
        for (int nj = 0; nj < 8; nj++)
#pragma unroll
            for (int r = 0; r < 4; r++) o[mi][nj][r] = 0.0f;

    const int NT = SEQ / ABKV;   // 32
    for (int t = 0; t < NT; t++) {
        CP_WAIT(1);
        __syncthreads();

        // ---- S = Q @ K^T : warp tile 32x32, fp16 k=16, 8 k-steps ----
        float sacc[2][4][4];
#pragma unroll
        for (int mi = 0; mi < 2; mi++)
#pragma unroll
            for (int ni = 0; ni < 4; ni++)
#pragma unroll
                for (int r = 0; r < 4; r++) sacc[mi][ni][r] = 0.0f;

#pragma unroll
        for (int ks = 0; ks < 8; ks++) {
            const int kk2 = ks * 8;
            uint32_t af[2][4], bf[4][2];
#pragma unroll
            for (int mi = 0; mi < 2; mi++) {
                int m = wm * 32 + mi * 16;
                af[mi][0] = Qs[(m + g) * LQK + kk2 + tig];
                af[mi][1] = Qs[(m + g + 8) * LQK + kk2 + tig];
                af[mi][2] = Qs[(m + g) * LQK + kk2 + tig + 4];
                af[mi][3] = Qs[(m + g + 8) * LQK + kk2 + tig + 4];
            }
#pragma unroll
            for (int ni = 0; ni < 4; ni++) {
                int n = wn * 32 + ni * 8;
                bf[ni][0] = Ks[(n + g) * LQK + kk2 + tig];
                bf[ni][1] = Ks[(n + g) * LQK + kk2 + tig + 4];
            }
#pragma unroll
            for (int mi = 0; mi < 2; mi++)
#pragma unroll
                for (int ni = 0; ni < 4; ni++)
                    mma_f16(sacc[mi][ni], af[mi], bf[ni]);
        }

        // ---- warp-local row maxes ----
#pragma unroll
        for (int mi = 0; mi < 2; mi++) {
            float a = -INFINITY, c = -INFINITY;
#pragma unroll
            for (int ni = 0; ni < 4; ni++) {
                a = fmaxf(a, fmaxf(sacc[mi][ni][0], sacc[mi][ni][1]));
                c = fmaxf(c, fmaxf(sacc[mi][ni][2], sacc[mi][ni][3]));
            }
            a = fmaxf(a, __shfl_xor_sync(0xFFFFFFFF, a, 1));
            a = fmaxf(a, __shfl_xor_sync(0xFFFFFFFF, a, 2));
            c = fmaxf(c, __shfl_xor_sync(0xFFFFFFFF, c, 1));
            c = fmaxf(c, __shfl_xor_sync(0xFFFFFFFF, c, 2));
            if (tig == 0) {
                maxbuf[wn * ABQ + rowA0 + mi * 16]     = a;
                maxbuf[wn * ABQ + rowA0 + mi * 16 + 8] = c;
            }
        }
        __syncthreads();   // Ks consumed + maxbuf visible

        // ---- prefetch K(t+1) ----
        if (t + 1 < NT) {
            const __half* Kn = K + base + (size_t)(t + 1) * ABKV * HIDDEN;
#pragma unroll
            for (int c = 0; c < 4; c++)
                cp_async16(ks_u32 + krow * (LQK * 4) + (kch0 + c) * 16,
                           Kn + (size_t)krow * HIDDEN + (kch0 + c) * 8);
            CP_COMMIT();
        }

        // ---- softmax: combine maxes, exp, write P (fp16) ----
        float sc[4], lsum[4];
#pragma unroll
        for (int i = 0; i < 4; i++) {
            int row = rowA0 + (i >> 1) * 16 + (i & 1) * 8;
            float mn = fmaxf(mreg[i], fmaxf(maxbuf[row], maxbuf[ABQ + row]));
            sc[i] = __expf(mreg[i] - mn);
            mreg[i] = mn;
            lsum[i] = 0.0f;
        }
#pragma unroll
        for (int mi = 0; mi < 2; mi++) {
            int rA = rowA0 + mi * 16;
#pragma unroll
            for (int ni = 0; ni < 4; ni++) {
                int cw = wn * 16 + ni * 4 + tig;   // u32 word offset in P row
                __half2 h0 = __floats2half2_rn(__expf(sacc[mi][ni][0] - mreg[mi * 2]),
                                               __expf(sacc[mi][ni][1] - mreg[mi * 2]));
                __half2 h1 = __floats2half2_rn(__expf(sacc[mi][ni][2] - mreg[mi * 2 + 1]),
                                               __expf(sacc[mi][ni][3] - mreg[mi * 2 + 1]));
                float2 f0 = __half22float2(h0);
                float2 f1 = __half22float2(h1);
                lsum[mi * 2]     += f0.x + f0.y;
                lsum[mi * 2 + 1] += f1.x + f1.y;
                Pu[rA * LPW + cw]       = *(uint32_t*)&h0;
                Pu[(rA + 8) * LPW + cw] = *(uint32_t*)&h1;
            }
        }
#pragma unroll
        for (int i = 0; i < 4; i++) {
            float ls = lsum[i];
            ls += __shfl_xor_sync(0xFFFFFFFF, ls, 1);
            ls += __shfl_xor_sync(0xFFFFFFFF, ls, 2);
            lsum[i] = ls;
        }
        if (tig == 0) {
#pragma unroll
            for (int i = 0; i < 4; i++) {
                int row = rowA0 + (i >> 1) * 16 + (i & 1) * 8;
                lbuf[wn * ABQ + row] = lsum[i];
            }
        }

        if (t + 1 < NT) { CP_WAIT(1); } else { CP_WAIT(0); }
        __syncthreads();   // P + lbuf visible, Vs(t) resident

#pragma unroll
        for (int i = 0; i < 4; i++) {
            int row = rowA0 + (i >> 1) * 16 + (i & 1) * 8;
            lreg[i] = lreg[i] * sc[i] + lbuf[row] + lbuf[ABQ + row];
        }

        // ---- O rescale + O += P @ V : warp tile 32x64, fp16 k=16, 4 steps ----
#pragma unroll
        for (int mi = 0; mi < 2; mi++) {
            float s0 = sc[mi * 2], s1 = sc[mi * 2 + 1];
#pragma unroll
            for (int nj = 0; nj < 8; nj++) {
                o[mi][nj][0] *= s0; o[mi][nj][1] *= s0;
                o[mi][nj][2] *= s1; o[mi][nj][3] *= s1;
            }
        }
#pragma unroll
        for (int ks = 0; ks < 4; ks++) {
            const int kk2 = ks * 8;          // P word offset (16 halves)
            const int kv0 = ks * 16;         // V row
            uint32_t af[2][4], bf[8][2];
#pragma unroll
            for (int mi = 0; mi < 2; mi++) {
                int m = wm * 32 + mi * 16;
                af[mi][0] = Pu[(m + g) * LPW + kk2 + tig];
                af[mi][1] = Pu[(m + g + 8) * LPW + kk2 + tig];
                af[mi][2] = Pu[(m + g) * LPW + kk2 + tig + 4];
                af[mi][3] = Pu[(m + g + 8) * LPW + kk2 + tig + 4];
            }
            // V fragments via ldmatrix.trans: rows kv0 + (lane&15), col n
            const uint32_t vrow_addr = vs_u32 + (kv0 + (lane & 15)) * (LVW * 4);
#pragma unroll
            for (int nj = 0; nj < 8; nj++) {
                int n = wn * 64 + nj * 8;
                ldsm_x2_trans(bf[nj][0], bf[nj][1], vrow_addr + n * 2);
            }
#pragma unroll
            for (int mi = 0; mi < 2; mi++)
#pragma unroll
                for (int nj = 0; nj < 8; nj++)
                    mma_f16(o[mi][nj], af[mi], bf[nj]);
        }
        __syncthreads();   // Vs consumed

        // ---- prefetch V(t+1) ----
        if (t + 1 < NT) {
            const __half* Vn = V + base + (size_t)(t + 1) * ABKV * HIDDEN;
#pragma unroll
            for (int c = 0; c < 4; c++)
                cp_async16(vs_u32 + krow * (LVW * 4) + (kch0 + c) * 16,
                           Vn + (size_t)krow * HIDDEN + (kch0 + c) * 8);
            CP_COMMIT();
        }
    }

    // ---- Epilogue: normalize, store fp16 ----
#pragma unroll
    for (int mi = 0; mi < 2; mi++) {
        int r0 = wm * 32 + mi * 16 + g;
        float inv0 = 1.0f / lreg[mi * 2];
        float inv1 = 1.0f / lreg[mi * 2 + 1];
#pragma unroll
        for (int nj = 0; nj < 8; nj++) {
            int col = wn * 64 + nj * 8 + tig * 2;
            __half2 a = __floats2half2_rn(o[mi][nj][0] * inv0, o[mi][nj][1] * inv0);
            __half2 c = __floats2half2_rn(o[mi][nj][2] * inv1, o[mi][nj][3] * inv1);
            *(__half2*)(O + base + (size_t)(q0 + r0) * HIDDEN + col)     = a;
            *(__half2*)(O + base + (size_t)(q0 + r0 + 8) * HIDDEN + col) = c;
        }
    }
}

// ---------------------------------------------------------------------------
// Launch
// ---------------------------------------------------------------------------
extern "C" void kernel_launch(void* const* d_in, const int* in_sizes, int n_in,
                              void* d_out, int out_size)
{
    (void)in_sizes; (void)n_in; (void)out_size;

    const float* hs = (const float*)d_in[0];
    const float* wq = (const float*)d_in[1];
    const float* bq = (const float*)d_in[2];
    const float* wk = (const float*)d_in[3];
    const float* bk = (const float*)d_in[4];
    const float* wv = (const float*)d_in[5];
    const float* bv = (const float*)d_in[6];
    const float* wo = (const float*)d_in[7];
    const float* bo = (const float*)d_in[8];
    float* out = (float*)d_out;

    float *bqs;
    __half *q, *k, *v, *ao, *hsr, *wqr, *wkr, *wvr, *wor;
    cudaGetSymbolAddress((void**)&q,   g_q);
    cudaGetSymbolAddress((void**)&k,   g_k);
    cudaGetSymbolAddress((void**)&v,   g_v);
    cudaGetSymbolAddress((void**)&ao,  g_ao);
    cudaGetSymbolAddress((void**)&hsr, g_hs);
    cudaGetSymbolAddress((void**)&wqr, g_wq);
    cudaGetSymbolAddress((void**)&wkr, g_wk);
    cudaGetSymbolAddress((void**)&wvr, g_wv);
    cudaGetSymbolAddress((void**)&wor, g_wo);
    cudaGetSymbolAddress((void**)&bqs, g_bqs);

    cudaFuncSetAttribute(attn_f16_kernel,
                         cudaFuncAttributeMaxDynamicSharedMemorySize,
                         ATTN_SMEM_BYTES);
    cudaFuncSetAttribute(gemm_f16_kernel,
                         cudaFuncAttributeMaxDynamicSharedMemorySize,
                         GEMM_SMEM_BYTES);

    const float scale = 0.08838834764831845f;  // 1/sqrt(128)

    // ---- prep ----
    const int nh4 = MTOK * HIDDEN / 4;
    prep_round_half<<<nh4 / 256, 256>>>(hs, hsr, 1.0f, nh4);
    dim3 tgrid(HIDDEN / 32, HIDDEN / 32), tblk(32, 8);
    prep_transpose_half<<<tgrid, tblk>>>(wq, wqr, scale);
    prep_transpose_half<<<tgrid, tblk>>>(wk, wkr, 1.0f);
    prep_transpose_half<<<tgrid, tblk>>>(wv, wvr, 1.0f);
    prep_transpose_half<<<tgrid, tblk>>>(wo, wor, 1.0f);
    prep_scale_kernel<<<HIDDEN / 4 / 64, 64>>>(bq, bqs, scale, HIDDEN / 4);

    dim3 gemm_grid(HIDDEN / GBN, MTOK / GBM);   // (16, 32)

    // QKV projections -> fp16 outputs
    gemm_f16_kernel<<<gemm_grid, 256, GEMM_SMEM_BYTES>>>(hsr, wqr, bqs, nullptr, q);
    gemm_f16_kernel<<<gemm_grid, 256, GEMM_SMEM_BYTES>>>(hsr, wkr, bk,  nullptr, k);
    gemm_f16_kernel<<<gemm_grid, 256, GEMM_SMEM_BYTES>>>(hsr, wvr, bv,  nullptr, v);

    dim3 attn_grid(SEQ / ABQ, NHEADS, BATCH);   // (16, 16, 2)
    attn_f16_kernel<<<attn_grid, 256, ATTN_SMEM_BYTES>>>(q, k, v, ao);

    // Output projection -> fp32
    gemm_f16_kernel<<<gemm_grid, 256, GEMM_SMEM_BYTES>>>(ao, wor, bo, out, nullptr);
}

// round 15
// speedup vs baseline: 6.2494x; 1.1096x over previous
#include <cuda_runtime.h>
#include <cuda_fp16.h>
#include <math.h>
#include <stdint.h>

// Problem constants (fixed by the reference)
#define HIDDEN 2048
#define NHEADS 16
#define HEADDIM 128
#define BATCH 2
#define SEQ 2048
#define MTOK (BATCH * SEQ)   // 4096

// ---------------------------------------------------------------------------
// Scratch buffers (allocation-free rule: __device__ globals)
// ---------------------------------------------------------------------------
__device__ __half g_q[MTOK * HIDDEN];        // fp16 Q (pre-scaled)
__device__ __half g_k[MTOK * HIDDEN];        // fp16 K
__device__ __half g_v[MTOK * HIDDEN];        // fp16 V
__device__ __half g_ao[MTOK * HIDDEN];       // attention out fp16
__device__ __half g_hs[MTOK * HIDDEN];       // fp16 hidden states
__device__ __half g_wq[HIDDEN * HIDDEN];     // fp16(scale*wq)^T  [N][K]
__device__ __half g_wk[HIDDEN * HIDDEN];
__device__ __half g_wv[HIDDEN * HIDDEN];
__device__ __half g_wo[HIDDEN * HIDDEN];
__device__ float  g_bqs[HIDDEN];             // scale * bq

__device__ __forceinline__ void mma_f16(float* c, const uint32_t* a, const uint32_t* b) {
    asm volatile(
        "mma.sync.aligned.m16n8k16.row.col.f32.f16.f16.f32 "
        "{%0,%1,%2,%3}, {%4,%5,%6,%7}, {%8,%9}, {%0,%1,%2,%3};\n"
        : "+f"(c[0]), "+f"(c[1]), "+f"(c[2]), "+f"(c[3])
        : "r"(a[0]), "r"(a[1]), "r"(a[2]), "r"(a[3]), "r"(b[0]), "r"(b[1]));
}

__device__ __forceinline__ void ldsm_x4(uint32_t& r0, uint32_t& r1,
                                        uint32_t& r2, uint32_t& r3, uint32_t addr) {
    asm volatile("ldmatrix.sync.aligned.m8n8.x4.shared.b16 {%0,%1,%2,%3}, [%4];"
                 : "=r"(r0), "=r"(r1), "=r"(r2), "=r"(r3) : "r"(addr));
}

__device__ __forceinline__ void ldsm_x2_trans(uint32_t& r0, uint32_t& r1, uint32_t addr) {
    asm volatile("ldmatrix.sync.aligned.m8n8.x2.trans.shared.b16 {%0,%1}, [%2];"
                 : "=r"(r0), "=r"(r1) : "r"(addr));
}

__device__ __forceinline__ void cp_async16(uint32_t smem_addr, const void* gptr) {
    asm volatile("cp.async.cg.shared.global [%0], [%1], 16;"
                 :: "r"(smem_addr), "l"(gptr));
}
#define CP_COMMIT() asm volatile("cp.async.commit_group;" ::: "memory")
#define CP_WAIT(N)  asm volatile("cp.async.wait_group %0;" :: "n"(N) : "memory")

__device__ __forceinline__ uint32_t smem_u32(const void* p) {
    return (uint32_t)__cvta_generic_to_shared(p);
}

// ---------------------------------------------------------------------------
// Prep kernels
// ---------------------------------------------------------------------------
__global__ void prep_round_half(const float* __restrict__ src,
                                __half* __restrict__ dst,
                                float mul, int n4)
{
    int i = blockIdx.x * blockDim.x + threadIdx.x;
    if (i < n4) {
        float4 v = *(const float4*)(src + i * 4);
        *(__half2*)(dst + i * 4)     = __floats2half2_rn(v.x * mul, v.y * mul);
        *(__half2*)(dst + i * 4 + 2) = __floats2half2_rn(v.z * mul, v.w * mul);
    }
}

__global__ void prep_scale_kernel(const float* __restrict__ src,
                                  float* __restrict__ dst,
                                  float mul, int n4)
{
    int i = blockIdx.x * blockDim.x + threadIdx.x;
    if (i < n4) {
        float4 v = *(const float4*)(src + i * 4);
        float4 o = { v.x * mul, v.y * mul, v.z * mul, v.w * mul };
        *(float4*)(dst + i * 4) = o;
    }
}

// W[K][N] -> Wt[N][K] fp16 (with optional scale)
__global__ void prep_transpose_half(const float* __restrict__ src,
                                    __half* __restrict__ dst, float mul)
{
    __shared__ float t[32][33];
    int bx = blockIdx.x * 32, by = blockIdx.y * 32;
    int tx = threadIdx.x, ty = threadIdx.y;
#pragma unroll
    for (int j = 0; j < 4; j++)
        t[ty + 8 * j][tx] = src[(size_t)(by + ty + 8 * j) * HIDDEN + bx + tx];
    __syncthreads();
#pragma unroll
    for (int j = 0; j < 4; j++)
        dst[(size_t)(bx + ty + 8 * j) * HIDDEN + by + tx] =
            __float2half_rn(t[tx][ty + 8 * j] * mul);
}

// ---------------------------------------------------------------------------
// FP16 tensor-core GEMM: C = A[M,K](f16) @ Wt[N,K](f16)^T + bias
// 128x128x64 tile, 256 thr, 2 CTA/SM, 2-stage cp.async, ldmatrix fragments.
// ---------------------------------------------------------------------------
#define GBM 128
#define GBN 128
#define GBK 64
#define GRS 36    // row stride in u32 words (64 halves = 32 words + 4 pad)
#define GRB (GRS * 4)                      // 144 B row stride
#define G_STG_WORDS (GBM * GRS)
#define GEMM_SMEM_BYTES (4 * G_STG_WORDS * 4)   // 73728

__global__ __launch_bounds__(256, 2)
void gemm_f16_kernel(const __half* __restrict__ A,
                     const __half* __restrict__ Wt,
                     const float* __restrict__ bias,
                     float* __restrict__ Cf,
                     __half* __restrict__ Ch)
{
    extern __shared__ uint32_t gsm[];
    uint32_t* Asm = gsm;
    uint32_t* Bsm = gsm + 2 * G_STG_WORDS;
    const uint32_t as_u32 = smem_u32(Asm);
    const uint32_t bs_u32 = smem_u32(Bsm);

    const int tid  = threadIdx.x;
    const int lane = tid & 31;
    const int warp = tid >> 5;
    const int wm   = warp >> 2;      // 0..1 -> rows wm*64
    const int wn   = warp & 3;       // 0..3 -> cols wn*32
    const int g    = lane >> 2;
    const int tig  = lane & 3;

    const int bm = blockIdx.y * GBM;
    const int bn = blockIdx.x * GBN;

    // ldmatrix per-lane address components
    const int gl      = lane & 7;
    const int a_roff  = ((lane >> 3) & 1) * 8 + gl;   // A: T0/T2 rows 0-7, T1/T3 +8
    const int a_coff  = (lane >> 4) * 16;             // A: T2/T3 second 16B chunk
    const int b_roff  = (lane >> 4) * 8 + gl;         // B: T2/T3 rows +8
    const int b_coff  = ((lane >> 3) & 1) * 16;       // B: T1/T3 second 16B chunk

    const int f_row = tid >> 1;
    const int f_ch0 = (tid & 1) * 4;

    auto fill = [&](int kt) {
        const int s = kt & 1;
        const __half* Ag = A  + (size_t)bm * HIDDEN + kt * GBK;
        const __half* Bg = Wt + (size_t)bn * HIDDEN + kt * GBK;
        const uint32_t abase = as_u32 + s * G_STG_WORDS * 4;
        const uint32_t bbase = bs_u32 + s * G_STG_WORDS * 4;
#pragma unroll
        for (int c = 0; c < 4; c++) {
            int ch = f_ch0 + c;
            cp_async16(abase + f_row * GRB + ch * 16,
                       Ag + (size_t)f_row * HIDDEN + ch * 8);
            cp_async16(bbase + f_row * GRB + ch * 16,
                       Bg + (size_t)f_row * HIDDEN + ch * 8);
        }
        CP_COMMIT();
    };

    float acc[4][4][4];
#pragma unroll
    for (int mi = 0; mi < 4; mi++)
#pragma unroll
        for (int ni = 0; ni < 4; ni++)
#pragma unroll
            for (int r = 0; r < 4; r++) acc[mi][ni][r] = 0.0f;

    const int nk = HIDDEN / GBK;   // 32
    fill(0);

    for (int kt = 0; kt < nk; kt++) {
        if (kt + 1 < nk) { fill(kt + 1); CP_WAIT(1); }
        else             { CP_WAIT(0); }
        __syncthreads();

        const uint32_t abase = as_u32 + (kt & 1) * G_STG_WORDS * 4;
        const uint32_t bbase = bs_u32 + (kt & 1) * G_STG_WORDS * 4;
#pragma unroll
        for (int ks = 0; ks < 4; ks++) {
            const int kb = ks * 32;   // byte offset of 16-half k-chunk
            uint32_t af[4][4], bf[4][2];
#pragma unroll
            for (int mi = 0; mi < 4; mi++) {
                int m = wm * 64 + mi * 16;
                ldsm_x4(af[mi][0], af[mi][1], af[mi][2], af[mi][3],
                        abase + (m + a_roff) * GRB + kb + a_coff);
            }
#pragma unroll
            for (int p = 0; p < 2; p++) {
                int n = wn * 32 + p * 16;
                ldsm_x4(bf[2 * p][0], bf[2 * p][1], bf[2 * p + 1][0], bf[2 * p + 1][1],
                        bbase + (n + b_roff) * GRB + kb + b_coff);
            }
#pragma unroll
            for (int mi = 0; mi < 4; mi++)
#pragma unroll
                for (int ni = 0; ni < 4; ni++)
                    mma_f16(acc[mi][ni], af[mi], bf[ni]);
        }
        __syncthreads();
    }

    // ---- epilogue ----
#pragma unroll
    for (int ni = 0; ni < 4; ni++) {
        int col = bn + wn * 32 + ni * 8 + tig * 2;
        float b0 = bias[col], b1 = bias[col + 1];
#pragma unroll
        for (int mi = 0; mi < 4; mi++) {
            int row = bm + wm * 64 + mi * 16 + g;
            float v00 = acc[mi][ni][0] + b0, v01 = acc[mi][ni][1] + b1;
            float v10 = acc[mi][ni][2] + b0, v11 = acc[mi][ni][3] + b1;
            if (Ch) {
                *(__half2*)(Ch + (size_t)row * HIDDEN + col)       = __floats2half2_rn(v00, v01);
                *(__half2*)(Ch + (size_t)(row + 8) * HIDDEN + col) = __floats2half2_rn(v10, v11);
            } else {
                float2 r0 = { v00, v01 };
                float2 r1 = { v10, v11 };
                *(float2*)(Cf + (size_t)row * HIDDEN + col)       = r0;
                *(float2*)(Cf + (size_t)(row + 8) * HIDDEN + col) = r1;
            }
        }
    }
}

// ---------------------------------------------------------------------------
// FP16 tensor-core flash attention, 256 threads, BQ=128, BKV=64.
// All mma fragments via ldmatrix. V via ldmatrix.trans.
// ---------------------------------------------------------------------------
#define ABQ 128
#define ABKV 64
#define LQK 68    // Q/K row stride, u32 words (272 B)
#define LVW 68    // V row stride
#define LPW 36    // P row stride (144 B)

#define AS_QS 0
#define AS_KS (AS_QS + ABQ * LQK)         // 8704
#define AS_VS (AS_KS + ABKV * LQK)        // 13056
#define AS_PS (AS_VS + ABKV * LVW)        // 17408
#define AS_MB (AS_PS + ABQ * LPW)         // 22016
#define AS_LB (AS_MB + 2 * ABQ)           // 22272
#define AS_TOT (AS_LB + 2 * ABQ)          // 22528 words
#define ATTN_SMEM_BYTES (AS_TOT * 4)      // 90112 B

__global__ __launch_bounds__(256)
void attn_f16_kernel(const __half* __restrict__ Q,
                     const __half* __restrict__ K,
                     const __half* __restrict__ V,
                     __half* __restrict__ O)
{
    extern __shared__ float sm[];
    uint32_t* Pu = (uint32_t*)(sm + AS_PS);
    float* maxbuf = sm + AS_MB;
    float* lbuf   = sm + AS_LB;
    const uint32_t qs_u32 = smem_u32(sm + AS_QS);
    const uint32_t ks_u32 = smem_u32(sm + AS_KS);
    const uint32_t vs_u32 = smem_u32(sm + AS_VS);
    const uint32_t ps_u32 = smem_u32(sm + AS_PS);

    const int tid  = threadIdx.x;
    const int lane = tid & 31;
    const int warp = tid >> 5;
    const int g    = lane >> 2;
    const int tig  = lane & 3;
    const int wm   = warp >> 1;    // 0..3 -> q rows wm*32
    const int wn   = warp & 1;     // 0..1 -> kv slab (S) / d slab (PV)

    const int q0 = blockIdx.x * ABQ;
    const int h  = blockIdx.y;
    const int b  = blockIdx.z;
    const size_t base = (size_t)b * SEQ * HIDDEN + (size_t)h * HEADDIM;

    const int rowA0 = wm * 32 + g;
    float mreg[4] = { -INFINITY, -INFINITY, -INFINITY, -INFINITY };
    float lreg[4] = { 0.0f, 0.0f, 0.0f, 0.0f };

    // ldmatrix per-lane address components
    const int gl     = lane & 7;
    const int a_roff = ((lane >> 3) & 1) * 8 + gl;
    const int a_coff = (lane >> 4) * 16;
    const int b_roff = (lane >> 4) * 8 + gl;
    const int b_coff = ((lane >> 3) & 1) * 16;

    const int qrow = tid >> 1, qch0 = (tid & 1) * 8;
    const int krow = tid >> 2, kch0 = (tid & 3) * 4;

    // ---- prologue: Q, K(0), V(0) ----
#pragma unroll
    for (int c = 0; c < 8; c++)
        cp_async16(qs_u32 + qrow * (LQK * 4) + (qch0 + c) * 16,
                   Q + base + (size_t)(q0 + qrow) * HIDDEN + (qch0 + c) * 8);
    CP_COMMIT();
#pragma unroll
    for (int c = 0; c < 4; c++)
        cp_async16(ks_u32 + krow * (LQK * 4) + (kch0 + c) * 16,
                   K + base + (size_t)krow * HIDDEN + (kch0 + c) * 8);
    CP_COMMIT();
#pragma unroll
    for (int c = 0; c < 4; c++)
        cp_async16(vs_u32 + krow * (LVW * 4) + (kch0 + c) * 16,
                   V + base + (size_t)krow * HIDDEN + (kch0 + c) * 8);
    CP_COMMIT();

    float o[2][8][4];
#pragma unroll
    for (int mi = 0; mi < 2; mi++)
#pragma unroll
        for (int nj = 0; nj < 8; nj++)
#pragma unroll
            for (int r = 0; r < 4; r++) o[mi][nj][r] = 0.0f;

    const int NT = SEQ / ABKV;   // 32
    for (int t = 0; t < NT; t++) {
        CP_WAIT(1);
        __syncthreads();

        // ---- S = Q @ K^T : warp tile 32x32, 8 k-steps, ldmatrix frags ----
        float sacc[2][4][4];
#pragma unroll
        for (int mi = 0; mi < 2; mi++)
#pragma unroll
            for (int ni = 0; ni < 4; ni++)
#pragma unroll
                for (int r = 0; r < 4; r++) sacc[mi][ni][r] = 0.0f;

#pragma unroll
        for (int ks = 0; ks < 8; ks++) {
            const int kb = ks * 32;
            uint32_t af[2][4], bf[4][2];
#pragma unroll
            for (int mi = 0; mi < 2; mi++) {
                int m = wm * 32 + mi * 16;
                ldsm_x4(af[mi][0], af[mi][1], af[mi][2], af[mi][3],
                        qs_u32 + (m + a_roff) * (LQK * 4) + kb + a_coff);
            }
#pragma unroll
            for (int p = 0; p < 2; p++) {
                int n = wn * 32 + p * 16;
                ldsm_x4(bf[2 * p][0], bf[2 * p][1], bf[2 * p + 1][0], bf[2 * p + 1][1],
                        ks_u32 + (n + b_roff) * (LQK * 4) + kb + b_coff);
            }
#pragma unroll
            for (int mi = 0; mi < 2; mi++)
#pragma unroll
                for (int ni = 0; ni < 4; ni++)
                    mma_f16(sacc[mi][ni], af[mi], bf[ni]);
        }

        // ---- warp-local row maxes ----
#pragma unroll
        for (int mi = 0; mi < 2; mi++) {
            float a = -INFINITY, c = -INFINITY;
#pragma unroll
            for (int ni = 0; ni < 4; ni++) {
                a = fmaxf(a, fmaxf(sacc[mi][ni][0], sacc[mi][ni][1]));
                c = fmaxf(c, fmaxf(sacc[mi][ni][2], sacc[mi][ni][3]));
            }
            a = fmaxf(a, __shfl_xor_sync(0xFFFFFFFF, a, 1));
            a = fmaxf(a, __shfl_xor_sync(0xFFFFFFFF, a, 2));
            c = fmaxf(c, __shfl_xor_sync(0xFFFFFFFF, c, 1));
            c = fmaxf(c, __shfl_xor_sync(0xFFFFFFFF, c, 2));
            if (tig == 0) {
                maxbuf[wn * ABQ + rowA0 + mi * 16]     = a;
                maxbuf[wn * ABQ + rowA0 + mi * 16 + 8] = c;
            }
        }
        __syncthreads();   // Ks consumed + maxbuf visible

        // ---- prefetch K(t+1) ----
        if (t + 1 < NT) {
            const __half* Kn = K + base + (size_t)(t + 1) * ABKV * HIDDEN;
#pragma unroll
            for (int c = 0; c < 4; c++)
                cp_async16(ks_u32 + krow * (LQK * 4) + (kch0 + c) * 16,
                           Kn + (size_t)krow * HIDDEN + (kch0 + c) * 8);
            CP_COMMIT();
        }

        // ---- softmax: combine maxes, exp, write P (fp16) ----
        float sc[4], lsum[4];
#pragma unroll
        for (int i = 0; i < 4; i++) {
            int row = rowA0 + (i >> 1) * 16 + (i & 1) * 8;
            float mn = fmaxf(mreg[i], fmaxf(maxbuf[row], maxbuf[ABQ + row]));
            sc[i] = __expf(mreg[i] - mn);
            mreg[i] = mn;
            lsum[i] = 0.0f;
        }
#pragma unroll
        for (int mi = 0; mi < 2; mi++) {
            int rA = rowA0 + mi * 16;
#pragma unroll
            for (int ni = 0; ni < 4; ni++) {
                int cw = wn * 16 + ni * 4 + tig;
                __half2 h0 = __floats2half2_rn(__expf(sacc[mi][ni][0] - mreg[mi * 2]),
                                               __expf(sacc[mi][ni][1] - mreg[mi * 2]));
                __half2 h1 = __floats2half2_rn(__expf(sacc[mi][ni][2] - mreg[mi * 2 + 1]),
                                               __expf(sacc[mi][ni][3] - mreg[mi * 2 + 1]));
                float2 f0 = __half22float2(h0);
                float2 f1 = __half22float2(h1);
                lsum[mi * 2]     += f0.x + f0.y;
                lsum[mi * 2 + 1] += f1.x + f1.y;
                Pu[rA * LPW + cw]       = *(uint32_t*)&h0;
                Pu[(rA + 8) * LPW + cw] = *(uint32_t*)&h1;
            }
        }
#pragma unroll
        for (int i = 0; i < 4; i++) {
            float ls = lsum[i];
            ls += __shfl_xor_sync(0xFFFFFFFF, ls, 1);
            ls += __shfl_xor_sync(0xFFFFFFFF, ls, 2);
            lsum[i] = ls;
        }
        if (tig == 0) {
#pragma unroll
            for (int i = 0; i < 4; i++) {
                int row = rowA0 + (i >> 1) * 16 + (i & 1) * 8;
                lbuf[wn * ABQ + row] = lsum[i];
            }
        }

        if (t + 1 < NT) { CP_WAIT(1); } else { CP_WAIT(0); }
        __syncthreads();   // P + lbuf visible, Vs(t) resident

#pragma unroll
        for (int i = 0; i < 4; i++) {
            int row = rowA0 + (i >> 1) * 16 + (i & 1) * 8;
            lreg[i] = lreg[i] * sc[i] + lbuf[row] + lbuf[ABQ + row];
        }

        // ---- O rescale + O += P @ V : warp tile 32x64, 4 k-steps ----
#pragma unroll
        for (int mi = 0; mi < 2; mi++) {
            float s0 = sc[mi * 2], s1 = sc[mi * 2 + 1];
#pragma unroll
            for (int nj = 0; nj < 8; nj++) {
                o[mi][nj][0] *= s0; o[mi][nj][1] *= s0;
                o[mi][nj][2] *= s1; o[mi][nj][3] *= s1;
            }
        }
#pragma unroll
        for (int ks = 0; ks < 4; ks++) {
            const int kb = ks * 32;          // P byte offset (16 halves)
            const int kv0 = ks * 16;         // V row
            uint32_t af[2][4], bf[8][2];
#pragma unroll
            for (int mi = 0; mi < 2; mi++) {
                int m = wm * 32 + mi * 16;
                ldsm_x4(af[mi][0], af[mi][1], af[mi][2], af[mi][3],
                        ps_u32 + (m + a_roff) * (LPW * 4) + kb + a_coff);
            }
            const uint32_t vrow_addr = vs_u32 + (kv0 + (lane & 15)) * (LVW * 4);
#pragma unroll
            for (int nj = 0; nj < 8; nj++) {
                int n = wn * 64 + nj * 8;
                ldsm_x2_trans(bf[nj][0], bf[nj][1], vrow_addr + n * 2);
            }
#pragma unroll
            for (int mi = 0; mi < 2; mi++)
#pragma unroll
                for (int nj = 0; nj < 8; nj++)
                    mma_f16(o[mi][nj], af[mi], bf[nj]);
        }
        __syncthreads();   // Vs consumed

        // ---- prefetch V(t+1) ----
        if (t + 1 < NT) {
            const __half* Vn = V + base + (size_t)(t + 1) * ABKV * HIDDEN;
#pragma unroll
            for (int c = 0; c < 4; c++)
                cp_async16(vs_u32 + krow * (LVW * 4) + (kch0 + c) * 16,
                           Vn + (size_t)krow * HIDDEN + (kch0 + c) * 8);
            CP_COMMIT();
        }
    }

    // ---- Epilogue: normalize, store fp16 ----
#pragma unroll
    for (int mi = 0; mi < 2; mi++) {
        int r0 = wm * 32 + mi * 16 + g;
        float inv0 = 1.0f / lreg[mi * 2];
        float inv1 = 1.0f / lreg[mi * 2 + 1];
#pragma unroll
        for (int nj = 0; nj < 8; nj++) {
            int col = wn * 64 + nj * 8 + tig * 2;
            __half2 a = __floats2half2_rn(o[mi][nj][0] * inv0, o[mi][nj][1] * inv0);
            __half2 c = __floats2half2_rn(o[mi][nj][2] * inv1, o[mi][nj][3] * inv1);
            *(__half2*)(O + base + (size_t)(q0 + r0) * HIDDEN + col)     = a;
            *(__half2*)(O + base + (size_t)(q0 + r0 + 8) * HIDDEN + col) = c;
        }
    }
}

// ---------------------------------------------------------------------------
// Launch
// ---------------------------------------------------------------------------
extern "C" void kernel_launch(void* const* d_in, const int* in_sizes, int n_in,
                              void* d_out, int out_size)
{
    (void)in_sizes; (void)n_in; (void)out_size;

    const float* hs = (const float*)d_in[0];
    const float* wq = (const float*)d_in[1];
    const float* bq = (const float*)d_in[2];
    const float* wk = (const float*)d_in[3];
    const float* bk = (const float*)d_in[4];
    const float* wv = (const float*)d_in[5];
    const float* bv = (const float*)d_in[6];
    const float* wo = (const float*)d_in[7];
    const float* bo = (const float*)d_in[8];
    float* out = (float*)d_out;

    float *bqs;
    __half *q, *k, *v, *ao, *hsr, *wqr, *wkr, *wvr, *wor;
    cudaGetSymbolAddress((void**)&q,   g_q);
    cudaGetSymbolAddress((void**)&k,   g_k);
    cudaGetSymbolAddress((void**)&v,   g_v);
    cudaGetSymbolAddress((void**)&ao,  g_ao);
    cudaGetSymbolAddress((void**)&hsr, g_hs);
    cudaGetSymbolAddress((void**)&wqr, g_wq);
    cudaGetSymbolAddress((void**)&wkr, g_wk);
    cudaGetSymbolAddress((void**)&wvr, g_wv);
    cudaGetSymbolAddress((void**)&wor, g_wo);
    cudaGetSymbolAddress((void**)&bqs, g_bqs);

    cudaFuncSetAttribute(attn_f16_kernel,
                         cudaFuncAttributeMaxDynamicSharedMemorySize,
                         ATTN_SMEM_BYTES);
    cudaFuncSetAttribute(gemm_f16_kernel,
                         cudaFuncAttributeMaxDynamicSharedMemorySize,
                         GEMM_SMEM_BYTES);

    const float scale = 0.08838834764831845f;  // 1/sqrt(128)

    // ---- prep ----
    const int nh4 = MTOK * HIDDEN / 4;
    prep_round_half<<<nh4 / 256, 256>>>(hs, hsr, 1.0f, nh4);
    dim3 tgrid(HIDDEN / 32, HIDDEN / 32), tblk(32, 8);
    prep_transpose_half<<<tgrid, tblk>>>(wq, wqr, scale);
    prep_transpose_half<<<tgrid, tblk>>>(wk, wkr, 1.0f);
    prep_transpose_half<<<tgrid, tblk>>>(wv, wvr, 1.0f);
    prep_transpose_half<<<tgrid, tblk>>>(wo, wor, 1.0f);
    prep_scale_kernel<<<HIDDEN / 4 / 64, 64>>>(bq, bqs, scale, HIDDEN / 4);

    dim3 gemm_grid(HIDDEN / GBN, MTOK / GBM);   // (16, 32)

    // QKV projections -> fp16 outputs
    gemm_f16_kernel<<<gemm_grid, 256, GEMM_SMEM_BYTES>>>(hsr, wqr, bqs, nullptr, q);
    gemm_f16_kernel<<<gemm_grid, 256, GEMM_SMEM_BYTES>>>(hsr, wkr, bk,  nullptr, k);
    gemm_f16_kernel<<<gemm_grid, 256, GEMM_SMEM_BYTES>>>(hsr, wvr, bv,  nullptr, v);

    dim3 attn_grid(SEQ / ABQ, NHEADS, BATCH);   // (16, 16, 2)
    attn_f16_kernel<<<attn_grid, 256, ATTN_SMEM_BYTES>>>(q, k, v, ao);

    // Output projection -> fp32
    gemm_f16_kernel<<<gemm_grid, 256, GEMM_SMEM_BYTES>>>(ao, wor, bo, out, nullptr);
}